// round 6
// baseline (speedup 1.0000x reference)
#include <cuda_runtime.h>
#include <cuda_bf16.h>
#include <cstdint>

#define SS 8
#define NN 2048
#define KK 64
#define NPAIR (SS * NN / 2)
#define PI_F 3.14159265358979323846f

// ---------------- precomputed tables (written by precompute_kernel) ----------
__device__ float g_td[4][31];      // td table per type-pair
__device__ float g_base[4][64];    // td @ gw0[:31] + gb0
__device__ float g_v[64];          // gw0[31,:]
// W^T fragments in mma.sync B-register layout: [nt(16)][ks(4)][lane(32)] -> {b0,b1}
__device__ uint2 g_bfrag_hi[2048];
__device__ uint2 g_bfrag_lo[2048];

// ---------------- helpers ----------------------------------------------------
__device__ __forceinline__ uint32_t smem_u32(const void* p) {
    uint32_t a;
    asm("{ .reg .u64 t; cvta.to.shared.u64 t, %1; cvt.u32.u64 %0, t; }" : "=r"(a) : "l"(p));
    return a;
}
__device__ __forceinline__ void ldm4(uint32_t* r, uint32_t addr) {
    asm volatile("ldmatrix.sync.aligned.m8n8.x4.shared.b16 {%0,%1,%2,%3}, [%4];"
                 : "=r"(r[0]), "=r"(r[1]), "=r"(r[2]), "=r"(r[3]) : "r"(addr));
}
__device__ __forceinline__ void mma16816(float* c, const uint32_t* a, uint2 b) {
    asm volatile("mma.sync.aligned.m16n8k16.row.col.f32.bf16.bf16.f32 "
                 "{%0,%1,%2,%3}, {%4,%5,%6,%7}, {%8,%9}, {%0,%1,%2,%3};"
                 : "+f"(c[0]), "+f"(c[1]), "+f"(c[2]), "+f"(c[3])
                 : "r"(a[0]), "r"(a[1]), "r"(a[2]), "r"(a[3]), "r"(b.x), "r"(b.y));
}
__device__ __forceinline__ uint32_t pack_bf16x2(float lo, float hi) {
    __nv_bfloat16 l = __float2bfloat16(lo);
    __nv_bfloat16 h = __float2bfloat16(hi);
    return (uint32_t)__bfloat16_as_ushort(l) | ((uint32_t)__bfloat16_as_ushort(h) << 16);
}
__device__ __forceinline__ float u16f(unsigned short u) {
    return __uint_as_float((uint32_t)u << 16);
}

// ---------------- tiny precompute: 4 type pairs + W fragment pack ------------
__global__ void precompute_kernel(const float* __restrict__ ew0, const float* __restrict__ eb0,
                                  const float* __restrict__ ew1, const float* __restrict__ eb1,
                                  const float* __restrict__ fw0, const float* __restrict__ fb0,
                                  const float* __restrict__ fw1, const float* __restrict__ fb1,
                                  const float* __restrict__ gw0, const float* __restrict__ gb0,
                                  const float* __restrict__ gw1) {
    __shared__ float td_s[4][31];
    int t = threadIdx.x;
    if (t < 4) {
        float a = (float)(t >> 1);
        float b = (float)(t & 1);
        float h32[32];
        for (int o = 0; o < 32; ++o) h32[o] = 0.f;
        for (int rev = 0; rev < 2; ++rev) {
            float x0 = rev ? b : a;
            float x1 = rev ? a : b;
            float h16[16];
            for (int i = 0; i < 16; ++i)
                h16[i] = fmaxf(x0 * ew0[i] + x1 * ew0[16 + i] + eb0[i], 0.f);
            for (int o = 0; o < 32; ++o) {
                float acc = eb1[o];
                for (int i = 0; i < 16; ++i) acc += h16[i] * ew1[i * 32 + o];
                h32[o] += fmaxf(acc, 0.f);
            }
        }
        float hf[32];
        for (int o = 0; o < 32; ++o) {
            float acc = fb0[o];
            for (int i = 0; i < 32; ++i) acc += h32[i] * fw0[i * 32 + o];
            hf[o] = fmaxf(acc, 0.f);
        }
        for (int o = 0; o < 31; ++o) {
            float acc = fb1[o];
            for (int i = 0; i < 32; ++i) acc += hf[i] * fw1[i * 31 + o];
            float td = fmaxf(acc, 0.f);
            td_s[t][o] = td;
            g_td[t][o] = td;
        }
    }
    __syncthreads();
    if (t < 64) {
        g_v[t] = gw0[31 * 64 + t];
        for (int p = 0; p < 4; ++p) {
            float acc = gb0[t];
            for (int i = 0; i < 31; ++i) acc += td_s[p][i] * gw0[i * 64 + t];
            g_base[p][t] = acc;
        }
    }
    // B fragments: mma.sync m16n8k16 col-major B layout
    for (int idx = t; idx < 2048; idx += 128) {
        int lane = idx & 31;
        int ks   = (idx >> 5) & 3;
        int nt   = idx >> 7;
        int e    = nt * 8 + (lane >> 2);
        int j0   = ks * 16 + (lane & 3) * 2;
        float w00 = gw1[j0 * 128 + e];
        float w01 = gw1[(j0 + 1) * 128 + e];
        float w10 = gw1[(j0 + 8) * 128 + e];
        float w11 = gw1[(j0 + 9) * 128 + e];
        float h00 = __bfloat162float(__float2bfloat16(w00));
        float h01 = __bfloat162float(__float2bfloat16(w01));
        float h10 = __bfloat162float(__float2bfloat16(w10));
        float h11 = __bfloat162float(__float2bfloat16(w11));
        g_bfrag_hi[idx] = make_uint2(pack_bf16x2(h00, h01), pack_bf16x2(h10, h11));
        g_bfrag_lo[idx] = make_uint2(pack_bf16x2(w00 - h00, w01 - h01),
                                     pack_bf16x2(w10 - h10, w11 - h11));
    }
}

// ---------------- dynamic SMEM layout ----------------------------------------
static constexpr int OFF_YHI  = 0;        // 16384 : 128 rows x 128B, XOR-swizzled
static constexpr int OFF_YLO  = 16384;    // 16384
static constexpr int OFF_BLO  = 32768;    // 16384 : W-lo fragments (uint2[2048])
static constexpr int OFF_RTS  = 49152;    // 2048  : float4[128]
static constexpr int OFF_BASE = 51200;    // 1088  : 4 x 68 floats
static constexpr int OFF_V    = 52288;    // 256
static constexpr int OFF_TD   = 52544;    // 528   : 4 x 33 floats
static constexpr int OFF_AS   = 53088;    // 4096  : float4[2][128]  (16B aligned)
static constexpr int SMEM_TOTAL = 57184;

// ---------------- fused main kernel: one CTA per 2 (s,n) pairs ---------------
__global__ __launch_bounds__(128, 4)
void desc_kernel(const float* __restrict__ inputs,
                 const int*   __restrict__ types,
                 const int*   __restrict__ neigh,
                 const float* __restrict__ length,
                 const float* __restrict__ gb1,
                 float*       __restrict__ out)
{
    extern __shared__ __align__(128) unsigned char smem[];
    unsigned char* yhi  = smem + OFF_YHI;
    unsigned char* ylo  = smem + OFF_YLO;
    uint2*  blo_s  = (uint2*)(smem + OFF_BLO);
    float4* rts4   = (float4*)(smem + OFF_RTS);
    float*  base_s = (float*)(smem + OFF_BASE);
    float*  v_s    = (float*)(smem + OFF_V);
    float*  td_s   = (float*)(smem + OFF_TD);
    float4* A_s    = (float4*)(smem + OFF_AS);
    const unsigned short* yhi16 = (const unsigned short*)yhi;
    const unsigned short* ylo16 = (const unsigned short*)ylo;

    const int t    = threadIdx.x;
    const int w    = t >> 5;
    const int lane = t & 31;

    // ---- W-hi fragments in registers; W-lo staged to smem ----
    uint2 bhi[4][4];
#pragma unroll
    for (int ntl = 0; ntl < 4; ++ntl)
#pragma unroll
        for (int ks = 0; ks < 4; ++ks)
            bhi[ntl][ks] = g_bfrag_hi[(((w * 4 + ntl) * 4) + ks) * 32 + lane];
    {
        const uint4* src = (const uint4*)g_bfrag_lo;
        uint4* dst = (uint4*)blo_s;
#pragma unroll
        for (int i = 0; i < 8; ++i) dst[t + 128 * i] = src[t + 128 * i];
    }

    // ---- stage small tables (padded strides) ----
    for (int i = t; i < 256; i += 128) base_s[(i >> 6) * 68 + (i & 63)] = ((const float*)g_base)[i];
    if (t < 64) v_s[t] = g_v[t];
    for (int i = t; i < 124; i += 128) td_s[(i / 31) * 33 + (i % 31)] = ((const float*)g_td)[i];
    if (t < 4) { td_s[t * 33 + 31] = 0.f; td_s[t * 33 + 32] = 0.f; }

    // per-cc epilogue invariants: cc = ntl*2 + c; e = w*32 + ntl*8 + (lane&3)*2 + c
    float b1v[8];
    int   choff[8];   // u16-unit offset of y1[.][j] within a row, incl. swizzle
#pragma unroll
    for (int cc = 0; cc < 8; ++cc) {
        int e = w * 32 + (cc >> 1) * 8 + (lane & 3) * 2 + (cc & 1);
        int j = e & 63;
        b1v[cc]  = gb1[e];
        choff[cc] = (((j >> 3) ^ (lane >> 2)) << 3) + (j & 7);
    }

    // ---- geometry for k-row t: sn_local = t>>6, k = t&63 ----
    const int sn = blockIdx.x * 2 + (t >> 6);
    const int s  = sn >> 11;
    const int n  = sn & (NN - 1);
    float sij; int pp;
    {
        int idx = neigh[(size_t)sn * KK + (t & 63)];
        bool msk = idx < 0;
        int i0 = msk ? 0 : idx;
        float Lx = length[0], Ly = length[1], Lz = length[2];
        const float* pc = inputs + ((size_t)s * NN + n) * 3;
        const float* pn = inputs + ((size_t)s * NN + i0) * 3;
        float dx = pn[0] - pc[0];
        float dy = pn[1] - pc[1];
        float dz = pn[2] - pc[2];
        dx -= Lx * rintf(dx / Lx);
        dy -= Ly * rintf(dy / Ly);
        dz -= Lz * rintf(dz / Lz);
        float rsq = dx * dx + dy * dy + dz * dz;
        float r   = sqrtf(rsq > 0.f ? rsq : 1.0f);
        float inv = 1.0f / r;
        float sw;
        if (r < 6.0f)       sw = inv;
        else if (r < 12.0f) { float u = (r - 6.0f) * (1.0f / 6.0f);
                              sw = inv * (0.5f * cosf(PI_F * u) + 0.5f); }
        else                sw = 0.f;
        bool valid = (!msk) && (rsq > 0.f);
        sij = valid ? sw : 0.f;
        float f = sij * inv;
        rts4[t] = make_float4(sij, dx * f, dy * f, dz * f);
        int ct = types[(size_t)s * NN + n];
        int nt = types[(size_t)s * NN + i0];
        pp = ct * 2 + nt;
    }
    __syncthreads();   // tables + rts4 published

    // ---- phase 2: y row t -> bf16 hi/lo, swizzled 16B-chunk stores ----
    {
        const int rx = t & 7;
#pragma unroll
        for (int c = 0; c < 8; ++c) {
            uint32_t wh[4], wl[4];
#pragma unroll
            for (int q = 0; q < 4; ++q) {
                int jp = c * 4 + q;
                int j0 = 2 * jp, j1 = 2 * jp + 1;
                float y0 = fmaxf(base_s[pp * 68 + j0] + sij * v_s[j0], 0.f);
                float y1 = fmaxf(base_s[pp * 68 + j1] + sij * v_s[j1], 0.f);
                int j032 = j0 & 31, j132 = j1 & 31;
                y0 += (j032 < 31) ? td_s[pp * 33 + j032] : sij;
                y1 += (j132 < 31) ? td_s[pp * 33 + j132] : sij;
                float h0 = __bfloat162float(__float2bfloat16(y0));
                float h1 = __bfloat162float(__float2bfloat16(y1));
                wh[q] = pack_bf16x2(h0, h1);
                wl[q] = pack_bf16x2(y0 - h0, y1 - h1);
            }
            int off = t * 128 + (c ^ rx) * 16;
            *(uint4*)(yhi + off) = make_uint4(wh[0], wh[1], wh[2], wh[3]);
            *(uint4*)(ylo + off) = make_uint4(wl[0], wl[1], wl[2], wl[3]);
        }
    }
    __syncthreads();   // Y panels + blo_s ready

    const uint32_t yhi_b = smem_u32(yhi);
    const uint32_t ylo_b = smem_u32(ylo);
    const int bwarp = w * 512 + lane;   // base index into blo_s for this warp

    // ---- MMA + fused epilogue ----
#pragma unroll
    for (int h = 0; h < 2; ++h) {
        float part[8][4];
#pragma unroll
        for (int cc = 0; cc < 8; ++cc)
#pragma unroll
            for (int d = 0; d < 4; ++d) part[cc][d] = 0.f;

#pragma unroll
        for (int mtl = 0; mtl < 4; ++mtl) {
            const int mt = h * 4 + mtl;
            float acc[4][4];
#pragma unroll
            for (int ntl = 0; ntl < 4; ++ntl)
#pragma unroll
                for (int d = 0; d < 4; ++d) acc[ntl][d] = 0.f;

            const int arow  = mt * 16 + (lane & 15);
            const int arx   = arow & 7;
            const uint32_t abase = (uint32_t)(arow * 128);
#pragma unroll
            for (int ks = 0; ks < 4; ++ks) {
                uint32_t ah[4], al[4];
                uint32_t chsel = (uint32_t)(((ks * 2 + (lane >> 4)) ^ arx) * 16);
                ldm4(ah, yhi_b + abase + chsel);
                ldm4(al, ylo_b + abase + chsel);
                uint2 bl[4];
#pragma unroll
                for (int ntl = 0; ntl < 4; ++ntl) bl[ntl] = blo_s[bwarp + (ntl * 4 + ks) * 32];
#pragma unroll
                for (int ntl = 0; ntl < 4; ++ntl) mma16816(acc[ntl], ah, bhi[ntl][ks]);
#pragma unroll
                for (int ntl = 0; ntl < 4; ++ntl) mma16816(acc[ntl], ah, bl[ntl]);
#pragma unroll
                for (int ntl = 0; ntl < 4; ++ntl) mma16816(acc[ntl], al, bhi[ntl][ks]);
            }
            // epilogue for this m-tile: tail read back from Y panels
            const int r0 = mt * 16 + (lane >> 2);
            const float4 q0 = rts4[r0];
            const float4 q1 = rts4[r0 + 8];
            const uint32_t tb0 = (uint32_t)(r0 * 64);   // u16 units, row stride 64
#pragma unroll
            for (int cc = 0; cc < 8; ++cc) {
                const int ntl = cc >> 1, c = cc & 1;
                const uint32_t o0 = tb0 + choff[cc];
                float tail0 = u16f(yhi16[o0])       + u16f(ylo16[o0]);
                float tail1 = u16f(yhi16[o0 + 512]) + u16f(ylo16[o0 + 512]);
                float g0 = fmaxf(acc[ntl][c]     + b1v[cc], 0.f) + tail0;
                float g1 = fmaxf(acc[ntl][2 + c] + b1v[cc], 0.f) + tail1;
                part[cc][0] = fmaf(g0, q0.x, fmaf(g1, q1.x, part[cc][0]));
                part[cc][1] = fmaf(g0, q0.y, fmaf(g1, q1.y, part[cc][1]));
                part[cc][2] = fmaf(g0, q0.z, fmaf(g1, q1.z, part[cc][2]));
                part[cc][3] = fmaf(g0, q0.w, fmaf(g1, q1.w, part[cc][3]));
            }
        }

        // reduce across lane-groups sharing (lane&3): xor 4, 8, 16
#pragma unroll
        for (int cc = 0; cc < 8; ++cc)
#pragma unroll
            for (int d = 0; d < 4; ++d) {
                float v = part[cc][d];
                v += __shfl_xor_sync(0xffffffffu, v, 4);
                v += __shfl_xor_sync(0xffffffffu, v, 8);
                v += __shfl_xor_sync(0xffffffffu, v, 16);
                part[cc][d] = v;
            }
        if (lane < 4) {
#pragma unroll
            for (int cc = 0; cc < 8; ++cc) {
                int e = w * 32 + (cc >> 1) * 8 + lane * 2 + (cc & 1);
                A_s[h * 128 + e] = make_float4(part[cc][0], part[cc][1], part[cc][2], part[cc][3]);
            }
        }
    }
    __syncthreads();

    // ---- D[e,m] = sum_d A[e,d] * A[m,d] per sn-half ----
    const int e = t;
#pragma unroll
    for (int h = 0; h < 2; ++h) {
        float4 a = A_s[h * 128 + e];
        size_t gsn = (size_t)blockIdx.x * 2 + h;
        float4* op = (float4*)(out + (gsn * 128 + e) * 16);
#pragma unroll
        for (int m4 = 0; m4 < 4; ++m4) {
            float4 b0 = A_s[h * 128 + 4 * m4 + 0];
            float4 b1 = A_s[h * 128 + 4 * m4 + 1];
            float4 b2 = A_s[h * 128 + 4 * m4 + 2];
            float4 b3 = A_s[h * 128 + 4 * m4 + 3];
            float4 o;
            o.x = a.x * b0.x + a.y * b0.y + a.z * b0.z + a.w * b0.w;
            o.y = a.x * b1.x + a.y * b1.y + a.z * b1.z + a.w * b1.w;
            o.z = a.x * b2.x + a.y * b2.y + a.z * b2.z + a.w * b2.w;
            o.w = a.x * b3.x + a.y * b3.y + a.z * b3.z + a.w * b3.w;
            op[m4] = o;
        }
    }
}

// ---------------- launch -----------------------------------------------------
extern "C" void kernel_launch(void* const* d_in, const int* in_sizes, int n_in,
                              void* d_out, int out_size) {
    const float* inputs = (const float*)d_in[0];
    const int*   types  = (const int*)d_in[1];
    const int*   neigh  = (const int*)d_in[2];
    const float* length = (const float*)d_in[3];
    const float* ew0 = (const float*)d_in[4];
    const float* eb0 = (const float*)d_in[5];
    const float* ew1 = (const float*)d_in[6];
    const float* eb1 = (const float*)d_in[7];
    const float* fw0 = (const float*)d_in[8];
    const float* fb0 = (const float*)d_in[9];
    const float* fw1 = (const float*)d_in[10];
    const float* fb1 = (const float*)d_in[11];
    const float* gw0 = (const float*)d_in[12];
    const float* gb0 = (const float*)d_in[13];
    const float* gw1 = (const float*)d_in[14];
    const float* gb1 = (const float*)d_in[15];

    cudaFuncSetAttribute(desc_kernel, cudaFuncAttributeMaxDynamicSharedMemorySize, SMEM_TOTAL);

    precompute_kernel<<<1, 128>>>(ew0, eb0, ew1, eb1, fw0, fb0, fw1, fb1, gw0, gb0, gw1);
    desc_kernel<<<NPAIR, 128, SMEM_TOTAL>>>(inputs, types, neigh, length, gb1, (float*)d_out);
}

// round 7
// speedup vs baseline: 1.1177x; 1.1177x over previous
#include <cuda_runtime.h>
#include <cuda_bf16.h>
#include <cstdint>

#define SS 8
#define NN 2048
#define KK 64
#define NPAIR (SS * NN / 2)
#define PI_F 3.14159265358979323846f

// ---------------- precomputed tables (written by precompute_kernel) ----------
__device__ float g_td[4][31];      // td table per type-pair
__device__ float g_base[4][64];    // td @ gw0[:31] + gb0
__device__ float g_v[64];          // gw0[31,:]
// W^T fragments in mma.sync B-register layout: [nt(16)][ks(4)][lane(32)] -> {b0,b1}
__device__ uint2 g_bfrag_hi[2048];
__device__ uint2 g_bfrag_lo[2048];

// ---------------- helpers ----------------------------------------------------
__device__ __forceinline__ uint32_t smem_u32(const void* p) {
    uint32_t a;
    asm("{ .reg .u64 t; cvta.to.shared.u64 t, %1; cvt.u32.u64 %0, t; }" : "=r"(a) : "l"(p));
    return a;
}
__device__ __forceinline__ void ldm4(uint32_t* r, uint32_t addr) {
    asm volatile("ldmatrix.sync.aligned.m8n8.x4.shared.b16 {%0,%1,%2,%3}, [%4];"
                 : "=r"(r[0]), "=r"(r[1]), "=r"(r[2]), "=r"(r[3]) : "r"(addr));
}
__device__ __forceinline__ void mma16816(float* c, const uint32_t* a, uint2 b) {
    asm volatile("mma.sync.aligned.m16n8k16.row.col.f32.bf16.bf16.f32 "
                 "{%0,%1,%2,%3}, {%4,%5,%6,%7}, {%8,%9}, {%0,%1,%2,%3};"
                 : "+f"(c[0]), "+f"(c[1]), "+f"(c[2]), "+f"(c[3])
                 : "r"(a[0]), "r"(a[1]), "r"(a[2]), "r"(a[3]), "r"(b.x), "r"(b.y));
}
__device__ __forceinline__ uint32_t pack_bf16x2(float lo, float hi) {
    __nv_bfloat16 l = __float2bfloat16(lo);
    __nv_bfloat16 h = __float2bfloat16(hi);
    return (uint32_t)__bfloat16_as_ushort(l) | ((uint32_t)__bfloat16_as_ushort(h) << 16);
}
__device__ __forceinline__ float u16f(unsigned short u) {
    return __uint_as_float((uint32_t)u << 16);
}

// ---------------- tiny precompute: 4 type pairs + W fragment pack ------------
__global__ void precompute_kernel(const float* __restrict__ ew0, const float* __restrict__ eb0,
                                  const float* __restrict__ ew1, const float* __restrict__ eb1,
                                  const float* __restrict__ fw0, const float* __restrict__ fb0,
                                  const float* __restrict__ fw1, const float* __restrict__ fb1,
                                  const float* __restrict__ gw0, const float* __restrict__ gb0,
                                  const float* __restrict__ gw1) {
    __shared__ float td_s[4][31];
    int t = threadIdx.x;
    if (t < 4) {
        float a = (float)(t >> 1);
        float b = (float)(t & 1);
        float h32[32];
        for (int o = 0; o < 32; ++o) h32[o] = 0.f;
        for (int rev = 0; rev < 2; ++rev) {
            float x0 = rev ? b : a;
            float x1 = rev ? a : b;
            float h16[16];
            for (int i = 0; i < 16; ++i)
                h16[i] = fmaxf(x0 * ew0[i] + x1 * ew0[16 + i] + eb0[i], 0.f);
            for (int o = 0; o < 32; ++o) {
                float acc = eb1[o];
                for (int i = 0; i < 16; ++i) acc += h16[i] * ew1[i * 32 + o];
                h32[o] += fmaxf(acc, 0.f);
            }
        }
        float hf[32];
        for (int o = 0; o < 32; ++o) {
            float acc = fb0[o];
            for (int i = 0; i < 32; ++i) acc += h32[i] * fw0[i * 32 + o];
            hf[o] = fmaxf(acc, 0.f);
        }
        for (int o = 0; o < 31; ++o) {
            float acc = fb1[o];
            for (int i = 0; i < 32; ++i) acc += hf[i] * fw1[i * 31 + o];
            float td = fmaxf(acc, 0.f);
            td_s[t][o] = td;
            g_td[t][o] = td;
        }
    }
    __syncthreads();
    if (t < 64) {
        g_v[t] = gw0[31 * 64 + t];
        for (int p = 0; p < 4; ++p) {
            float acc = gb0[t];
            for (int i = 0; i < 31; ++i) acc += td_s[p][i] * gw0[i * 64 + t];
            g_base[p][t] = acc;
        }
    }
    // B fragments: mma.sync m16n8k16 col-major B layout
    for (int idx = t; idx < 2048; idx += 128) {
        int lane = idx & 31;
        int ks   = (idx >> 5) & 3;
        int nt   = idx >> 7;
        int e    = nt * 8 + (lane >> 2);
        int j0   = ks * 16 + (lane & 3) * 2;
        float w00 = gw1[j0 * 128 + e];
        float w01 = gw1[(j0 + 1) * 128 + e];
        float w10 = gw1[(j0 + 8) * 128 + e];
        float w11 = gw1[(j0 + 9) * 128 + e];
        float h00 = __bfloat162float(__float2bfloat16(w00));
        float h01 = __bfloat162float(__float2bfloat16(w01));
        float h10 = __bfloat162float(__float2bfloat16(w10));
        float h11 = __bfloat162float(__float2bfloat16(w11));
        g_bfrag_hi[idx] = make_uint2(pack_bf16x2(h00, h01), pack_bf16x2(h10, h11));
        g_bfrag_lo[idx] = make_uint2(pack_bf16x2(w00 - h00, w01 - h01),
                                     pack_bf16x2(w10 - h10, w11 - h11));
    }
}

// ---------------- fused main kernel: one CTA per 2 (s,n) pairs ---------------
__global__ __launch_bounds__(128, 3)
void desc_kernel(const float* __restrict__ inputs,
                 const int*   __restrict__ types,
                 const int*   __restrict__ neigh,
                 const float* __restrict__ length,
                 const float* __restrict__ gb1,
                 float*       __restrict__ out)
{
    // Y panels: 128 rows x 64 bf16 (128B rows), 16B-chunk XOR swizzle (c ^= row&7)
    __shared__ __align__(128) unsigned char yhi[128 * 128];
    __shared__ __align__(128) unsigned char ylo[128 * 128];
    __shared__ __align__(16) float4 rts4[128];
    __shared__ __align__(16) float base_s[4 * 68];   // stride 68 -> bank=(4p+j)%32
    __shared__ __align__(16) float v_s[64];
    __shared__ __align__(16) float td_s[4 * 34];     // stride 34 -> bank=(2p+j)%32, 8B-aligned rows
    __shared__ __align__(16) float4 T_s[128];        // tail contribution: [snh(2)][j(64)]
    __shared__ __align__(16) float4 A_s[2][128];

    const int t    = threadIdx.x;
    const int w    = t >> 5;
    const int lane = t & 31;

    // ---- B fragment preload first (hide L2 latency behind phase 1/2) ----
    uint2 bhi[4][4], blo[4][4];
#pragma unroll
    for (int ntl = 0; ntl < 4; ++ntl)
#pragma unroll
        for (int ks = 0; ks < 4; ++ks) {
            int idx = (((w * 4 + ntl) * 4) + ks) * 32 + lane;
            bhi[ntl][ks] = g_bfrag_hi[idx];
            blo[ntl][ks] = g_bfrag_lo[idx];
        }

    // ---- stage tables (padded strides) ----
    for (int i = t; i < 256; i += 128) base_s[(i >> 6) * 68 + (i & 63)] = ((const float*)g_base)[i];
    if (t < 64) v_s[t] = g_v[t];
    for (int i = t; i < 124; i += 128) td_s[(i / 31) * 34 + (i % 31)] = ((const float*)g_td)[i];
    if (t < 4) { td_s[t * 34 + 31] = 0.f; td_s[t * 34 + 32] = 0.f; td_s[t * 34 + 33] = 0.f; }

    // per-cc epilogue invariants
    float b1v[8];
#pragma unroll
    for (int cc = 0; cc < 8; ++cc)
        b1v[cc] = gb1[w * 32 + (cc >> 1) * 8 + (lane & 3) * 2 + (cc & 1)];

    // ---- geometry for k-row t: sn_local = t>>6, k = t&63 ----
    const int sn = blockIdx.x * 2 + (t >> 6);
    const int s  = sn >> 11;
    const int n  = sn & (NN - 1);
    float sij; int pp;
    {
        int idx = neigh[(size_t)sn * KK + (t & 63)];
        bool msk = idx < 0;
        int i0 = msk ? 0 : idx;
        float Lx = length[0], Ly = length[1], Lz = length[2];
        const float* pc = inputs + ((size_t)s * NN + n) * 3;
        const float* pn = inputs + ((size_t)s * NN + i0) * 3;
        float dx = pn[0] - pc[0];
        float dy = pn[1] - pc[1];
        float dz = pn[2] - pc[2];
        dx -= Lx * rintf(dx / Lx);
        dy -= Ly * rintf(dy / Ly);
        dz -= Lz * rintf(dz / Lz);
        float rsq = dx * dx + dy * dy + dz * dz;
        float rs  = rsq > 0.f ? rsq : 1.0f;
        float inv = rsqrtf(rs);
        float r   = rs * inv;
        float sw;
        if (r < 6.0f)       sw = inv;
        else if (r < 12.0f) { float u = (r - 6.0f) * (1.0f / 6.0f);
                              sw = inv * (0.5f * __cosf(PI_F * u) + 0.5f); }
        else                sw = 0.f;
        bool valid = (!msk) && (rsq > 0.f);
        sij = valid ? sw : 0.f;
        float f = sij * inv;
        rts4[t] = make_float4(sij, dx * f, dy * f, dz * f);
        int ct = types[(size_t)s * NN + n];
        int nt = types[(size_t)s * NN + i0];
        pp = ct * 2 + nt;
    }
    __syncthreads();   // tables + rts4 published

    // ---- phase 2: y row t -> bf16 hi/lo, swizzled 16B-chunk stores ----
    {
        const int rx = t & 7;
        const float2* base2 = (const float2*)(base_s + pp * 68);
        const float2* v2    = (const float2*)v_s;
        const float2* td2   = (const float2*)(td_s + pp * 34);
#pragma unroll
        for (int c = 0; c < 8; ++c) {
            uint32_t wh[4], wl[4];
#pragma unroll
            for (int q = 0; q < 4; ++q) {
                int jp = c * 4 + q;
                float2 b  = base2[jp];
                float2 vv = v2[jp];
                float2 td = td2[jp & 15];
                // j0 = 2jp even => (j0&31) < 31 always; j1 tail is sij when (jp&15)==15
                float y0 = fmaxf(fmaf(sij, vv.x, b.x), 0.f) + td.x;
                float y1 = fmaxf(fmaf(sij, vv.y, b.y), 0.f) + (((jp & 15) < 15) ? td.y : sij);
                float h0 = __bfloat162float(__float2bfloat16(y0));
                float h1 = __bfloat162float(__float2bfloat16(y1));
                wh[q] = pack_bf16x2(h0, h1);
                wl[q] = pack_bf16x2(y0 - h0, y1 - h1);
            }
            int off = t * 128 + (c ^ rx) * 16;
            *(uint4*)(yhi + off) = make_uint4(wh[0], wh[1], wh[2], wh[3]);
            *(uint4*)(ylo + off) = make_uint4(wl[0], wl[1], wl[2], wl[3]);
        }
    }
    __syncthreads();   // Y panels ready

    const unsigned short* yhi16 = (const unsigned short*)yhi;
    const unsigned short* ylo16 = (const unsigned short*)ylo;

    // ---- tail contribution: T[j,d] = sum_k y1[k,j] * rt[k,d], per sn-half ----
    {
        const int snh = t >> 6, jt = t & 63;
        const int chunk = jt >> 3, jlow = jt & 7;
        float4 Tv = make_float4(0.f, 0.f, 0.f, 0.f);
#pragma unroll 4
        for (int k = 0; k < 64; ++k) {
            int row = snh * 64 + k;
            uint32_t o = (uint32_t)(row * 64 + ((chunk ^ (row & 7)) << 3) + jlow);
            float y = u16f(yhi16[o]) + u16f(ylo16[o]);
            float4 q = rts4[row];
            Tv.x = fmaf(y, q.x, Tv.x);
            Tv.y = fmaf(y, q.y, Tv.y);
            Tv.z = fmaf(y, q.z, Tv.z);
            Tv.w = fmaf(y, q.w, Tv.w);
        }
        T_s[t] = Tv;
    }
    __syncthreads();   // T_s published

    const uint32_t yhi_b = smem_u32(yhi);
    const uint32_t ylo_b = smem_u32(ylo);

    // ---- MMA + fused epilogue ----
#pragma unroll
    for (int h = 0; h < 2; ++h) {
        float part[8][4];
#pragma unroll
        for (int cc = 0; cc < 8; ++cc)
#pragma unroll
            for (int d = 0; d < 4; ++d) part[cc][d] = 0.f;

#pragma unroll
        for (int mtl = 0; mtl < 4; ++mtl) {
            const int mt = h * 4 + mtl;
            float acc[4][4];
#pragma unroll
            for (int ntl = 0; ntl < 4; ++ntl)
#pragma unroll
                for (int d = 0; d < 4; ++d) acc[ntl][d] = 0.f;

            const int arow  = mt * 16 + (lane & 15);
            const int arx   = arow & 7;
            const uint32_t abase = (uint32_t)(arow * 128);
#pragma unroll
            for (int ks = 0; ks < 4; ++ks) {
                uint32_t ah[4], al[4];
                uint32_t chsel = (uint32_t)(((ks * 2 + (lane >> 4)) ^ arx) * 16);
                ldm4(ah, yhi_b + abase + chsel);
                ldm4(al, ylo_b + abase + chsel);
                // term-major: dependency distance 4 on each accumulator
#pragma unroll
                for (int ntl = 0; ntl < 4; ++ntl) mma16816(acc[ntl], ah, bhi[ntl][ks]);
#pragma unroll
                for (int ntl = 0; ntl < 4; ++ntl) mma16816(acc[ntl], ah, blo[ntl][ks]);
#pragma unroll
                for (int ntl = 0; ntl < 4; ++ntl) mma16816(acc[ntl], al, bhi[ntl][ks]);
            }
            // epilogue for this m-tile: relu part only (tail folded into T)
            const int r0 = mt * 16 + (lane >> 2);
            const float4 q0 = rts4[r0];
            const float4 q1 = rts4[r0 + 8];
#pragma unroll
            for (int cc = 0; cc < 8; ++cc) {
                const int ntl = cc >> 1, c = cc & 1;
                float g0 = fmaxf(acc[ntl][c]     + b1v[cc], 0.f);
                float g1 = fmaxf(acc[ntl][2 + c] + b1v[cc], 0.f);
                part[cc][0] = fmaf(g0, q0.x, fmaf(g1, q1.x, part[cc][0]));
                part[cc][1] = fmaf(g0, q0.y, fmaf(g1, q1.y, part[cc][1]));
                part[cc][2] = fmaf(g0, q0.z, fmaf(g1, q1.z, part[cc][2]));
                part[cc][3] = fmaf(g0, q0.w, fmaf(g1, q1.w, part[cc][3]));
            }
        }

        // reduce across lane-groups sharing (lane&3): xor 4, 8, 16
#pragma unroll
        for (int cc = 0; cc < 8; ++cc)
#pragma unroll
            for (int d = 0; d < 4; ++d) {
                float v = part[cc][d];
                v += __shfl_xor_sync(0xffffffffu, v, 4);
                v += __shfl_xor_sync(0xffffffffu, v, 8);
                v += __shfl_xor_sync(0xffffffffu, v, 16);
                part[cc][d] = v;
            }
        if (lane < 4) {
#pragma unroll
            for (int cc = 0; cc < 8; ++cc) {
                int e = w * 32 + (cc >> 1) * 8 + lane * 2 + (cc & 1);
                float4 Tv = T_s[h * 64 + (e & 63)];
                A_s[h][e] = make_float4(part[cc][0] + Tv.x, part[cc][1] + Tv.y,
                                        part[cc][2] + Tv.z, part[cc][3] + Tv.w);
            }
        }
    }
    __syncthreads();

    // ---- D[e,m] = sum_d A[e,d] * A[m,d] per sn-half ----
    const int e = t;
#pragma unroll
    for (int h = 0; h < 2; ++h) {
        float4 a = A_s[h][e];
        size_t gsn = (size_t)blockIdx.x * 2 + h;
        float4* op = (float4*)(out + (gsn * 128 + e) * 16);
#pragma unroll
        for (int m4 = 0; m4 < 4; ++m4) {
            float4 b0 = A_s[h][4 * m4 + 0];
            float4 b1 = A_s[h][4 * m4 + 1];
            float4 b2 = A_s[h][4 * m4 + 2];
            float4 b3 = A_s[h][4 * m4 + 3];
            float4 o;
            o.x = a.x * b0.x + a.y * b0.y + a.z * b0.z + a.w * b0.w;
            o.y = a.x * b1.x + a.y * b1.y + a.z * b1.z + a.w * b1.w;
            o.z = a.x * b2.x + a.y * b2.y + a.z * b2.z + a.w * b2.w;
            o.w = a.x * b3.x + a.y * b3.y + a.z * b3.z + a.w * b3.w;
            op[m4] = o;
        }
    }
}

// ---------------- launch -----------------------------------------------------
extern "C" void kernel_launch(void* const* d_in, const int* in_sizes, int n_in,
                              void* d_out, int out_size) {
    const float* inputs = (const float*)d_in[0];
    const int*   types  = (const int*)d_in[1];
    const int*   neigh  = (const int*)d_in[2];
    const float* length = (const float*)d_in[3];
    const float* ew0 = (const float*)d_in[4];
    const float* eb0 = (const float*)d_in[5];
    const float* ew1 = (const float*)d_in[6];
    const float* eb1 = (const float*)d_in[7];
    const float* fw0 = (const float*)d_in[8];
    const float* fb0 = (const float*)d_in[9];
    const float* fw1 = (const float*)d_in[10];
    const float* fb1 = (const float*)d_in[11];
    const float* gw0 = (const float*)d_in[12];
    const float* gb0 = (const float*)d_in[13];
    const float* gw1 = (const float*)d_in[14];
    const float* gb1 = (const float*)d_in[15];

    precompute_kernel<<<1, 128>>>(ew0, eb0, ew1, eb1, fw0, fb0, fw1, fb1, gw0, gb0, gw1);
    desc_kernel<<<NPAIR, 128>>>(inputs, types, neigh, length, gb1, (float*)d_out);
}

// round 8
// speedup vs baseline: 1.2521x; 1.1203x over previous
#include <cuda_runtime.h>
#include <cuda_bf16.h>
#include <cstdint>

#define SS 8
#define NN 2048
#define KK 64
#define NPAIR (SS * NN / 2)
#define PI_F 3.14159265358979323846f

// ---------------- precomputed tables (written by precompute_kernel) ----------
__device__ float g_td[4][31];      // td table per type-pair
__device__ float g_base[4][64];    // td @ gw0[:31] + gb0
__device__ float g_v[64];          // gw0[31,:]
// W^T fragments in mma.sync B-register layout: [nt(16)][ks(4)][lane(32)] -> {b0,b1}
__device__ uint2 g_bfrag_hi[2048];
__device__ uint2 g_bfrag_lo[2048];

// ---------------- helpers ----------------------------------------------------
__device__ __forceinline__ uint32_t smem_u32(const void* p) {
    uint32_t a;
    asm("{ .reg .u64 t; cvta.to.shared.u64 t, %1; cvt.u32.u64 %0, t; }" : "=r"(a) : "l"(p));
    return a;
}
__device__ __forceinline__ void ldm4(uint32_t* r, uint32_t addr) {
    asm volatile("ldmatrix.sync.aligned.m8n8.x4.shared.b16 {%0,%1,%2,%3}, [%4];"
                 : "=r"(r[0]), "=r"(r[1]), "=r"(r[2]), "=r"(r[3]) : "r"(addr));
}
__device__ __forceinline__ void mma16816(float* c, const uint32_t* a, uint2 b) {
    asm volatile("mma.sync.aligned.m16n8k16.row.col.f32.bf16.bf16.f32 "
                 "{%0,%1,%2,%3}, {%4,%5,%6,%7}, {%8,%9}, {%0,%1,%2,%3};"
                 : "+f"(c[0]), "+f"(c[1]), "+f"(c[2]), "+f"(c[3])
                 : "r"(a[0]), "r"(a[1]), "r"(a[2]), "r"(a[3]), "r"(b.x), "r"(b.y));
}
__device__ __forceinline__ uint32_t pack_bf16x2(float lo, float hi) {
    __nv_bfloat16 l = __float2bfloat16(lo);
    __nv_bfloat16 h = __float2bfloat16(hi);
    return (uint32_t)__bfloat16_as_ushort(l) | ((uint32_t)__bfloat16_as_ushort(h) << 16);
}
__device__ __forceinline__ float u16f(unsigned short u) {
    return __uint_as_float((uint32_t)u << 16);
}
// packed f32x2 (proven to compile under this toolchain in R1)
typedef unsigned long long ull;
__device__ __forceinline__ ull pk2f(float lo, float hi) {
    ull r; asm("mov.b64 %0, {%1, %2};" : "=l"(r) : "f"(lo), "f"(hi)); return r;
}
__device__ __forceinline__ ull fma2(ull a, ull b, ull c) {
    ull d; asm("fma.rn.f32x2 %0, %1, %2, %3;" : "=l"(d) : "l"(a), "l"(b), "l"(c)); return d;
}
__device__ __forceinline__ float2 upk2(ull v) {
    float2 r; asm("mov.b64 {%0, %1}, %2;" : "=f"(r.x), "=f"(r.y) : "l"(v)); return r;
}

// ---------------- parallel precompute: 4 type pairs + W fragment pack --------
__global__ void precompute_kernel(const float* __restrict__ ew0, const float* __restrict__ eb0,
                                  const float* __restrict__ ew1, const float* __restrict__ eb1,
                                  const float* __restrict__ fw0, const float* __restrict__ fb0,
                                  const float* __restrict__ fw1, const float* __restrict__ fb1,
                                  const float* __restrict__ gw0, const float* __restrict__ gb0,
                                  const float* __restrict__ gw1) {
    __shared__ float sh16[2][4][16];
    __shared__ float sh32[4][32];
    __shared__ float shf[4][32];
    __shared__ float shtd[4][31];
    const int t = threadIdx.x;

    // stage A: h16[rev][p][i], 128-way parallel
    {
        int rev = t >> 6, p = (t >> 4) & 3, i = t & 15;
        float a = (float)(p >> 1), b = (float)(p & 1);
        float x0 = rev ? b : a, x1 = rev ? a : b;
        sh16[rev][p][i] = fmaxf(x0 * ew0[i] + x1 * ew0[16 + i] + eb0[i], 0.f);
    }
    __syncthreads();
    // stage B: h32[p][o] = relu(fwd) + relu(rev)
    {
        int p = t >> 5, o = t & 31;
        float s0 = eb1[o], s1 = eb1[o];
        for (int i = 0; i < 16; ++i) {
            s0 += sh16[0][p][i] * ew1[i * 32 + o];
            s1 += sh16[1][p][i] * ew1[i * 32 + o];
        }
        sh32[p][o] = fmaxf(s0, 0.f) + fmaxf(s1, 0.f);
    }
    __syncthreads();
    // stage C: hf[p][o]
    {
        int p = t >> 5, o = t & 31;
        float acc = fb0[o];
        for (int i = 0; i < 32; ++i) acc += sh32[p][i] * fw0[i * 32 + o];
        shf[p][o] = fmaxf(acc, 0.f);
    }
    __syncthreads();
    // stage D: td[p][o], 124 threads
    if (t < 124) {
        int p = t / 31, o = t % 31;
        float acc = fb1[o];
        for (int i = 0; i < 32; ++i) acc += shf[p][i] * fw1[i * 31 + o];
        float td = fmaxf(acc, 0.f);
        g_td[p][o] = td;
        shtd[p][o] = td;
    }
    __syncthreads();
    // stage E: base[p][j] + v
    for (int it = 0; it < 2; ++it) {
        int idx = t + 128 * it;
        int p = idx >> 6, j = idx & 63;
        float acc = gb0[j];
        for (int i = 0; i < 31; ++i) acc += shtd[p][i] * gw0[i * 64 + j];
        g_base[p][j] = acc;
    }
    if (t < 64) g_v[t] = gw0[31 * 64 + t];

    // B fragments: mma.sync m16n8k16 col-major B layout
    for (int idx = t; idx < 2048; idx += 128) {
        int lane = idx & 31;
        int ks   = (idx >> 5) & 3;
        int nt   = idx >> 7;
        int e    = nt * 8 + (lane >> 2);
        int j0   = ks * 16 + (lane & 3) * 2;
        float w00 = gw1[j0 * 128 + e];
        float w01 = gw1[(j0 + 1) * 128 + e];
        float w10 = gw1[(j0 + 8) * 128 + e];
        float w11 = gw1[(j0 + 9) * 128 + e];
        float h00 = __bfloat162float(__float2bfloat16(w00));
        float h01 = __bfloat162float(__float2bfloat16(w01));
        float h10 = __bfloat162float(__float2bfloat16(w10));
        float h11 = __bfloat162float(__float2bfloat16(w11));
        g_bfrag_hi[idx] = make_uint2(pack_bf16x2(h00, h01), pack_bf16x2(h10, h11));
        g_bfrag_lo[idx] = make_uint2(pack_bf16x2(w00 - h00, w01 - h01),
                                     pack_bf16x2(w10 - h10, w11 - h11));
    }
}

// ---------------- fused main kernel: one CTA per 2 (s,n) pairs ---------------
__global__ __launch_bounds__(128, 3)
void desc_kernel(const float* __restrict__ inputs,
                 const int*   __restrict__ types,
                 const int*   __restrict__ neigh,
                 const float* __restrict__ length,
                 const float* __restrict__ gb1,
                 float*       __restrict__ out)
{
    __shared__ __align__(128) unsigned char yhi[128 * 128];
    __shared__ __align__(128) unsigned char ylo[128 * 128];
    __shared__ __align__(16) float4 rts4[128];
    __shared__ __align__(16) float base_s[4 * 68];
    __shared__ __align__(16) float v_s[64];
    __shared__ __align__(16) float td_s[4 * 34];
    __shared__ __align__(16) float4 T_s[128];        // [snh(2)][j(64)]
    __shared__ __align__(16) float4 A_s[2][128];

    const int t    = threadIdx.x;
    const int w    = t >> 5;
    const int lane = t & 31;

    // ---- B fragment preload ----
    uint2 bhi[4][4], blo[4][4];
#pragma unroll
    for (int ntl = 0; ntl < 4; ++ntl)
#pragma unroll
        for (int ks = 0; ks < 4; ++ks) {
            int idx = (((w * 4 + ntl) * 4) + ks) * 32 + lane;
            bhi[ntl][ks] = g_bfrag_hi[idx];
            blo[ntl][ks] = g_bfrag_lo[idx];
        }

    // ---- stage tables ----
    for (int i = t; i < 256; i += 128) base_s[(i >> 6) * 68 + (i & 63)] = ((const float*)g_base)[i];
    if (t < 64) v_s[t] = g_v[t];
    for (int i = t; i < 124; i += 128) td_s[(i / 31) * 34 + (i % 31)] = ((const float*)g_td)[i];
    if (t < 4) { td_s[t * 34 + 31] = 0.f; td_s[t * 34 + 32] = 0.f; td_s[t * 34 + 33] = 0.f; }

    float b1v[8];
#pragma unroll
    for (int cc = 0; cc < 8; ++cc)
        b1v[cc] = gb1[w * 32 + (cc >> 1) * 8 + (lane & 3) * 2 + (cc & 1)];

    // ---- geometry ----
    const int sn = blockIdx.x * 2 + (t >> 6);
    const int s  = sn >> 11;
    const int n  = sn & (NN - 1);
    float sij; int pp;
    {
        int idx = neigh[(size_t)sn * KK + (t & 63)];
        bool msk = idx < 0;
        int i0 = msk ? 0 : idx;
        float Lx = length[0], Ly = length[1], Lz = length[2];
        const float* pc = inputs + ((size_t)s * NN + n) * 3;
        const float* pn = inputs + ((size_t)s * NN + i0) * 3;
        float dx = pn[0] - pc[0];
        float dy = pn[1] - pc[1];
        float dz = pn[2] - pc[2];
        dx -= Lx * rintf(dx / Lx);
        dy -= Ly * rintf(dy / Ly);
        dz -= Lz * rintf(dz / Lz);
        float rsq = dx * dx + dy * dy + dz * dz;
        float rs  = rsq > 0.f ? rsq : 1.0f;
        float inv = rsqrtf(rs);
        float r   = rs * inv;
        float sw;
        if (r < 6.0f)       sw = inv;
        else if (r < 12.0f) { float u = (r - 6.0f) * (1.0f / 6.0f);
                              sw = inv * (0.5f * __cosf(PI_F * u) + 0.5f); }
        else                sw = 0.f;
        bool valid = (!msk) && (rsq > 0.f);
        sij = valid ? sw : 0.f;
        float f = sij * inv;
        rts4[t] = make_float4(sij, dx * f, dy * f, dz * f);
        int ct = types[(size_t)s * NN + n];
        int nt = types[(size_t)s * NN + i0];
        pp = ct * 2 + nt;
    }
    __syncthreads();

    // ---- phase 2: y row t -> bf16 hi/lo ----
    {
        const int rx = t & 7;
        const float2* base2 = (const float2*)(base_s + pp * 68);
        const float2* v2    = (const float2*)v_s;
        const float2* td2   = (const float2*)(td_s + pp * 34);
#pragma unroll
        for (int c = 0; c < 8; ++c) {
            uint32_t wh[4], wl[4];
#pragma unroll
            for (int q = 0; q < 4; ++q) {
                int jp = c * 4 + q;
                float2 b  = base2[jp];
                float2 vv = v2[jp];
                float2 td = td2[jp & 15];
                float y0 = fmaxf(fmaf(sij, vv.x, b.x), 0.f) + td.x;
                float y1 = fmaxf(fmaf(sij, vv.y, b.y), 0.f) + (((jp & 15) < 15) ? td.y : sij);
                float h0 = __bfloat162float(__float2bfloat16(y0));
                float h1 = __bfloat162float(__float2bfloat16(y1));
                wh[q] = pack_bf16x2(h0, h1);
                wl[q] = pack_bf16x2(y0 - h0, y1 - h1);
            }
            int off = t * 128 + (c ^ rx) * 16;
            *(uint4*)(yhi + off) = make_uint4(wh[0], wh[1], wh[2], wh[3]);
            *(uint4*)(ylo + off) = make_uint4(wl[0], wl[1], wl[2], wl[3]);
        }
    }
    __syncthreads();

    const unsigned short* yhi16 = (const unsigned short*)yhi;
    const unsigned short* ylo16 = (const unsigned short*)ylo;

    // ---- tail: T[j,d] = sum_k y1[k,j] * rt[k,d]; packed f32x2, full unroll ----
    {
        const int snh = t >> 6, jt = t & 63;
        const int chunk = jt >> 3, jlow = jt & 7;
        const uint32_t ob = (uint32_t)(snh * 64 * 64 + jlow);
        ull T01 = 0ull, T23 = 0ull;
#pragma unroll
        for (int k = 0; k < 64; ++k) {
            uint32_t o = ob + (uint32_t)(k * 64 + ((chunk ^ (k & 7)) << 3));
            float y = u16f(yhi16[o]) + u16f(ylo16[o]);
            ull yp = pk2f(y, y);
            double2 q = *(const double2*)(rts4 + snh * 64 + k);
            T01 = fma2(yp, __double_as_longlong(q.x), T01);
            T23 = fma2(yp, __double_as_longlong(q.y), T23);
        }
        float2 a = upk2(T01), b = upk2(T23);
        T_s[t] = make_float4(a.x, a.y, b.x, b.y);
    }
    __syncthreads();

    const uint32_t yhi_b = smem_u32(yhi);
    const uint32_t ylo_b = smem_u32(ylo);

    // ---- MMA + fused epilogue ----
#pragma unroll
    for (int h = 0; h < 2; ++h) {
        ull part01[8], part23[8];
#pragma unroll
        for (int cc = 0; cc < 8; ++cc) { part01[cc] = 0ull; part23[cc] = 0ull; }

#pragma unroll
        for (int mtl = 0; mtl < 4; ++mtl) {
            const int mt = h * 4 + mtl;
            float acc[4][4];
#pragma unroll
            for (int ntl = 0; ntl < 4; ++ntl) {   // bias pre-folded into accumulator
                acc[ntl][0] = b1v[ntl * 2];
                acc[ntl][1] = b1v[ntl * 2 + 1];
                acc[ntl][2] = b1v[ntl * 2];
                acc[ntl][3] = b1v[ntl * 2 + 1];
            }

            const int arow  = mt * 16 + (lane & 15);
            const int arx   = arow & 7;
            const uint32_t abase = (uint32_t)(arow * 128);
#pragma unroll
            for (int ks = 0; ks < 4; ++ks) {
                uint32_t ah[4], al[4];
                uint32_t chsel = (uint32_t)(((ks * 2 + (lane >> 4)) ^ arx) * 16);
                ldm4(ah, yhi_b + abase + chsel);
                ldm4(al, ylo_b + abase + chsel);
#pragma unroll
                for (int ntl = 0; ntl < 4; ++ntl) mma16816(acc[ntl], ah, bhi[ntl][ks]);
#pragma unroll
                for (int ntl = 0; ntl < 4; ++ntl) mma16816(acc[ntl], ah, blo[ntl][ks]);
#pragma unroll
                for (int ntl = 0; ntl < 4; ++ntl) mma16816(acc[ntl], al, bhi[ntl][ks]);
            }
            // epilogue: relu + packed A-accumulation
            const int r0 = mt * 16 + (lane >> 2);
            double2 qa = *(const double2*)(rts4 + r0);
            double2 qb = *(const double2*)(rts4 + r0 + 8);
            const ull q0xy = __double_as_longlong(qa.x), q0zw = __double_as_longlong(qa.y);
            const ull q1xy = __double_as_longlong(qb.x), q1zw = __double_as_longlong(qb.y);
#pragma unroll
            for (int cc = 0; cc < 8; ++cc) {
                const int ntl = cc >> 1, c = cc & 1;
                float g0 = fmaxf(acc[ntl][c],     0.f);
                float g1 = fmaxf(acc[ntl][2 + c], 0.f);
                ull g0p = pk2f(g0, g0);
                ull g1p = pk2f(g1, g1);
                part01[cc] = fma2(g0p, q0xy, part01[cc]);
                part23[cc] = fma2(g0p, q0zw, part23[cc]);
                part01[cc] = fma2(g1p, q1xy, part01[cc]);
                part23[cc] = fma2(g1p, q1zw, part23[cc]);
            }
        }

        // unpack + reduce across lane-groups sharing (lane&3)
#pragma unroll
        for (int cc = 0; cc < 8; ++cc) {
            float2 u01 = upk2(part01[cc]);
            float2 u23 = upk2(part23[cc]);
            float pv[4] = {u01.x, u01.y, u23.x, u23.y};
#pragma unroll
            for (int d = 0; d < 4; ++d) {
                float v = pv[d];
                v += __shfl_xor_sync(0xffffffffu, v, 4);
                v += __shfl_xor_sync(0xffffffffu, v, 8);
                v += __shfl_xor_sync(0xffffffffu, v, 16);
                pv[d] = v;
            }
            if (lane < 4) {
                int e = w * 32 + (cc >> 1) * 8 + lane * 2 + (cc & 1);
                float4 Tv = T_s[h * 64 + (e & 63)];
                A_s[h][e] = make_float4(pv[0] + Tv.x, pv[1] + Tv.y,
                                        pv[2] + Tv.z, pv[3] + Tv.w);
            }
        }
    }
    __syncthreads();

    // ---- D[e,m] = sum_d A[e,d] * A[m,d] per sn-half ----
    const int e = t;
#pragma unroll
    for (int h = 0; h < 2; ++h) {
        float4 a = A_s[h][e];
        size_t gsn = (size_t)blockIdx.x * 2 + h;
        float4* op = (float4*)(out + (gsn * 128 + e) * 16);
#pragma unroll
        for (int m4 = 0; m4 < 4; ++m4) {
            float4 b0 = A_s[h][4 * m4 + 0];
            float4 b1 = A_s[h][4 * m4 + 1];
            float4 b2 = A_s[h][4 * m4 + 2];
            float4 b3 = A_s[h][4 * m4 + 3];
            float4 o;
            o.x = a.x * b0.x + a.y * b0.y + a.z * b0.z + a.w * b0.w;
            o.y = a.x * b1.x + a.y * b1.y + a.z * b1.z + a.w * b1.w;
            o.z = a.x * b2.x + a.y * b2.y + a.z * b2.z + a.w * b2.w;
            o.w = a.x * b3.x + a.y * b3.y + a.z * b3.z + a.w * b3.w;
            op[m4] = o;
        }
    }
}

// ---------------- launch -----------------------------------------------------
extern "C" void kernel_launch(void* const* d_in, const int* in_sizes, int n_in,
                              void* d_out, int out_size) {
    const float* inputs = (const float*)d_in[0];
    const int*   types  = (const int*)d_in[1];
    const int*   neigh  = (const int*)d_in[2];
    const float* length = (const float*)d_in[3];
    const float* ew0 = (const float*)d_in[4];
    const float* eb0 = (const float*)d_in[5];
    const float* ew1 = (const float*)d_in[6];
    const float* eb1 = (const float*)d_in[7];
    const float* fw0 = (const float*)d_in[8];
    const float* fb0 = (const float*)d_in[9];
    const float* fw1 = (const float*)d_in[10];
    const float* fb1 = (const float*)d_in[11];
    const float* gw0 = (const float*)d_in[12];
    const float* gb0 = (const float*)d_in[13];
    const float* gw1 = (const float*)d_in[14];
    const float* gb1 = (const float*)d_in[15];

    precompute_kernel<<<1, 128>>>(ew0, eb0, ew1, eb1, fw0, fb0, fw1, fb1, gw0, gb0, gw1);
    desc_kernel<<<NPAIR, 128>>>(inputs, types, neigh, length, gb1, (float*)d_out);
}

// round 9
// speedup vs baseline: 1.4987x; 1.1969x over previous
#include <cuda_runtime.h>
#include <cuda_fp16.h>
#include <cstdint>

#define SS 8
#define NN 2048
#define KK 64
#define NPAIR (SS * NN / 2)
#define PI_F 3.14159265358979323846f

// ---------------- precomputed tables (written by precompute_kernel) ----------
__device__ float g_td[4][31];      // td table per type-pair
__device__ float g_base[4][64];    // td @ gw0[:31] + gb0
__device__ float g_v[64];          // gw0[31,:]
// W^T fragments (fp16, unsplit) in mma.sync B layout: [nt(16)][ks(4)][lane(32)]
__device__ uint2 g_bfrag[2048];

// ---------------- helpers ----------------------------------------------------
__device__ __forceinline__ uint32_t smem_u32(const void* p) {
    uint32_t a;
    asm("{ .reg .u64 t; cvta.to.shared.u64 t, %1; cvt.u32.u64 %0, t; }" : "=r"(a) : "l"(p));
    return a;
}
__device__ __forceinline__ void ldm4(uint32_t* r, uint32_t addr) {
    asm volatile("ldmatrix.sync.aligned.m8n8.x4.shared.b16 {%0,%1,%2,%3}, [%4];"
                 : "=r"(r[0]), "=r"(r[1]), "=r"(r[2]), "=r"(r[3]) : "r"(addr));
}
__device__ __forceinline__ void mma16816(float* c, const uint32_t* a, uint2 b) {
    asm volatile("mma.sync.aligned.m16n8k16.row.col.f32.f16.f16.f32 "
                 "{%0,%1,%2,%3}, {%4,%5,%6,%7}, {%8,%9}, {%0,%1,%2,%3};"
                 : "+f"(c[0]), "+f"(c[1]), "+f"(c[2]), "+f"(c[3])
                 : "r"(a[0]), "r"(a[1]), "r"(a[2]), "r"(a[3]), "r"(b.x), "r"(b.y));
}
__device__ __forceinline__ uint32_t pack_h2(float lo, float hi) {
    __half l = __float2half_rn(lo);
    __half h = __float2half_rn(hi);
    return (uint32_t)__half_as_ushort(l) | ((uint32_t)__half_as_ushort(h) << 16);
}
// packed f32x2
typedef unsigned long long ull;
__device__ __forceinline__ ull pk2f(float lo, float hi) {
    ull r; asm("mov.b64 %0, {%1, %2};" : "=l"(r) : "f"(lo), "f"(hi)); return r;
}
__device__ __forceinline__ ull fma2(ull a, ull b, ull c) {
    ull d; asm("fma.rn.f32x2 %0, %1, %2, %3;" : "=l"(d) : "l"(a), "l"(b), "l"(c)); return d;
}
__device__ __forceinline__ float2 upk2(ull v) {
    float2 r; asm("mov.b64 {%0, %1}, %2;" : "=f"(r.x), "=f"(r.y) : "l"(v)); return r;
}

// ---------------- parallel precompute: 4 type pairs + W fragment pack --------
__global__ void precompute_kernel(const float* __restrict__ ew0, const float* __restrict__ eb0,
                                  const float* __restrict__ ew1, const float* __restrict__ eb1,
                                  const float* __restrict__ fw0, const float* __restrict__ fb0,
                                  const float* __restrict__ fw1, const float* __restrict__ fb1,
                                  const float* __restrict__ gw0, const float* __restrict__ gb0,
                                  const float* __restrict__ gw1) {
    __shared__ float sh16[2][4][16];
    __shared__ float sh32[4][32];
    __shared__ float shf[4][32];
    __shared__ float shtd[4][31];
    const int t = threadIdx.x;

    {
        int rev = t >> 6, p = (t >> 4) & 3, i = t & 15;
        float a = (float)(p >> 1), b = (float)(p & 1);
        float x0 = rev ? b : a, x1 = rev ? a : b;
        sh16[rev][p][i] = fmaxf(x0 * ew0[i] + x1 * ew0[16 + i] + eb0[i], 0.f);
    }
    __syncthreads();
    {
        int p = t >> 5, o = t & 31;
        float s0 = eb1[o], s1 = eb1[o];
        for (int i = 0; i < 16; ++i) {
            s0 += sh16[0][p][i] * ew1[i * 32 + o];
            s1 += sh16[1][p][i] * ew1[i * 32 + o];
        }
        sh32[p][o] = fmaxf(s0, 0.f) + fmaxf(s1, 0.f);
    }
    __syncthreads();
    {
        int p = t >> 5, o = t & 31;
        float acc = fb0[o];
        for (int i = 0; i < 32; ++i) acc += sh32[p][i] * fw0[i * 32 + o];
        shf[p][o] = fmaxf(acc, 0.f);
    }
    __syncthreads();
    if (t < 124) {
        int p = t / 31, o = t % 31;
        float acc = fb1[o];
        for (int i = 0; i < 32; ++i) acc += shf[p][i] * fw1[i * 31 + o];
        float td = fmaxf(acc, 0.f);
        g_td[p][o] = td;
        shtd[p][o] = td;
    }
    __syncthreads();
    for (int it = 0; it < 2; ++it) {
        int idx = t + 128 * it;
        int p = idx >> 6, j = idx & 63;
        float acc = gb0[j];
        for (int i = 0; i < 31; ++i) acc += shtd[p][i] * gw0[i * 64 + j];
        g_base[p][j] = acc;
    }
    if (t < 64) g_v[t] = gw0[31 * 64 + t];

    // B fragments: fp16, unsplit; mma.sync m16n8k16 col-major B layout
    for (int idx = t; idx < 2048; idx += 128) {
        int lane = idx & 31;
        int ks   = (idx >> 5) & 3;
        int nt   = idx >> 7;
        int e    = nt * 8 + (lane >> 2);
        int j0   = ks * 16 + (lane & 3) * 2;
        g_bfrag[idx] = make_uint2(
            pack_h2(gw1[j0 * 128 + e],       gw1[(j0 + 1) * 128 + e]),
            pack_h2(gw1[(j0 + 8) * 128 + e], gw1[(j0 + 9) * 128 + e]));
    }
}

// ---------------- fused main kernel: one CTA per 2 (s,n) pairs ---------------
__global__ __launch_bounds__(128, 4)
void desc_kernel(const float* __restrict__ inputs,
                 const int*   __restrict__ types,
                 const int*   __restrict__ neigh,
                 const float* __restrict__ length,
                 const float* __restrict__ gb1,
                 float*       __restrict__ out)
{
    __shared__ __align__(128) unsigned char yhi[128 * 128];
    __shared__ __align__(128) unsigned char ylo[128 * 128];
    __shared__ __align__(16) float4 rts4[128];
    __shared__ __align__(16) float base_s[4 * 68];
    __shared__ __align__(16) float v_s[64];
    __shared__ __align__(16) float td_s[4 * 34];
    __shared__ __align__(16) float4 T_s[128];        // [snh(2)][j(64)]
    __shared__ __align__(16) float4 A_s[2][128];

    const int t    = threadIdx.x;
    const int w    = t >> 5;
    const int lane = t & 31;

    // ---- B fragment preload (fp16, single set) ----
    uint2 bfr[4][4];
#pragma unroll
    for (int ntl = 0; ntl < 4; ++ntl)
#pragma unroll
        for (int ks = 0; ks < 4; ++ks)
            bfr[ntl][ks] = g_bfrag[(((w * 4 + ntl) * 4) + ks) * 32 + lane];

    // ---- stage tables ----
    for (int i = t; i < 256; i += 128) base_s[(i >> 6) * 68 + (i & 63)] = ((const float*)g_base)[i];
    if (t < 64) v_s[t] = g_v[t];
    for (int i = t; i < 124; i += 128) td_s[(i / 31) * 34 + (i % 31)] = ((const float*)g_td)[i];
    if (t < 4) { td_s[t * 34 + 31] = 0.f; td_s[t * 34 + 32] = 0.f; td_s[t * 34 + 33] = 0.f; }

    float b1v[8];
#pragma unroll
    for (int cc = 0; cc < 8; ++cc)
        b1v[cc] = gb1[w * 32 + (cc >> 1) * 8 + (lane & 3) * 2 + (cc & 1)];

    // ---- geometry ----
    const int sn = blockIdx.x * 2 + (t >> 6);
    const int s  = sn >> 11;
    const int n  = sn & (NN - 1);
    float sij; int pp;
    {
        int idx = neigh[(size_t)sn * KK + (t & 63)];
        bool msk = idx < 0;
        int i0 = msk ? 0 : idx;
        float Lx = length[0], Ly = length[1], Lz = length[2];
        const float* pc = inputs + ((size_t)s * NN + n) * 3;
        const float* pn = inputs + ((size_t)s * NN + i0) * 3;
        float dx = pn[0] - pc[0];
        float dy = pn[1] - pc[1];
        float dz = pn[2] - pc[2];
        dx -= Lx * rintf(dx / Lx);
        dy -= Ly * rintf(dy / Ly);
        dz -= Lz * rintf(dz / Lz);
        float rsq = dx * dx + dy * dy + dz * dz;
        float rs  = rsq > 0.f ? rsq : 1.0f;
        float inv = rsqrtf(rs);
        float r   = rs * inv;
        float sw;
        if (r < 6.0f)       sw = inv;
        else if (r < 12.0f) { float u = (r - 6.0f) * (1.0f / 6.0f);
                              sw = inv * (0.5f * __cosf(PI_F * u) + 0.5f); }
        else                sw = 0.f;
        bool valid = (!msk) && (rsq > 0.f);
        sij = valid ? sw : 0.f;
        float f = sij * inv;
        rts4[t] = make_float4(sij, dx * f, dy * f, dz * f);
        int ct = types[(size_t)s * NN + n];
        int nt = types[(size_t)s * NN + i0];
        pp = ct * 2 + nt;
    }
    __syncthreads();

    // ---- phase 2: y row t -> fp16 hi + fp16 residual, swizzled stores ----
    {
        const int rx = t & 7;
        const float2* base2 = (const float2*)(base_s + pp * 68);
        const float2* v2    = (const float2*)v_s;
        const float2* td2   = (const float2*)(td_s + pp * 34);
#pragma unroll
        for (int c = 0; c < 8; ++c) {
            uint32_t wh[4], wl[4];
#pragma unroll
            for (int q = 0; q < 4; ++q) {
                int jp = c * 4 + q;
                float2 b  = base2[jp];
                float2 vv = v2[jp];
                float2 td = td2[jp & 15];
                float y0 = fmaxf(fmaf(sij, vv.x, b.x), 0.f) + td.x;
                float y1 = fmaxf(fmaf(sij, vv.y, b.y), 0.f) + (((jp & 15) < 15) ? td.y : sij);
                __half h0 = __float2half_rn(y0);
                __half h1 = __float2half_rn(y1);
                float h0f = __half2float(h0);
                float h1f = __half2float(h1);
                wh[q] = (uint32_t)__half_as_ushort(h0) | ((uint32_t)__half_as_ushort(h1) << 16);
                wl[q] = pack_h2(y0 - h0f, y1 - h1f);
            }
            int off = t * 128 + (c ^ rx) * 16;
            *(uint4*)(yhi + off) = make_uint4(wh[0], wh[1], wh[2], wh[3]);
            *(uint4*)(ylo + off) = make_uint4(wl[0], wl[1], wl[2], wl[3]);
        }
    }
    __syncthreads();

    const __half* yhi16 = (const __half*)yhi;
    const __half* ylo16 = (const __half*)ylo;

    // ---- tail: T[j,d] = sum_k y1[k,j] * rt[k,d]; packed f32x2 ----
    {
        const int snh = t >> 6, jt = t & 63;
        const int chunk = jt >> 3, jlow = jt & 7;
        const uint32_t ob = (uint32_t)(snh * 64 * 64 + jlow);
        ull T01 = 0ull, T23 = 0ull;
#pragma unroll
        for (int k = 0; k < 64; ++k) {
            uint32_t o = ob + (uint32_t)(k * 64 + ((chunk ^ (k & 7)) << 3));
            float y = __half2float(yhi16[o]) + __half2float(ylo16[o]);
            ull yp = pk2f(y, y);
            double2 q = *(const double2*)(rts4 + snh * 64 + k);
            T01 = fma2(yp, __double_as_longlong(q.x), T01);
            T23 = fma2(yp, __double_as_longlong(q.y), T23);
        }
        float2 a = upk2(T01), b = upk2(T23);
        T_s[t] = make_float4(a.x, a.y, b.x, b.y);
    }
    __syncthreads();

    const uint32_t yhi_b = smem_u32(yhi);
    const uint32_t ylo_b = smem_u32(ylo);

    // ---- MMA + fused epilogue: G = (Yh + Yl) * Wh, 8 mma per (mt,ks) ----
#pragma unroll
    for (int h = 0; h < 2; ++h) {
        ull part01[8], part23[8];
#pragma unroll
        for (int cc = 0; cc < 8; ++cc) { part01[cc] = 0ull; part23[cc] = 0ull; }

#pragma unroll
        for (int mtl = 0; mtl < 4; ++mtl) {
            const int mt = h * 4 + mtl;
            float acc[4][4];
#pragma unroll
            for (int ntl = 0; ntl < 4; ++ntl) {   // bias pre-folded
                acc[ntl][0] = b1v[ntl * 2];
                acc[ntl][1] = b1v[ntl * 2 + 1];
                acc[ntl][2] = b1v[ntl * 2];
                acc[ntl][3] = b1v[ntl * 2 + 1];
            }

            const int arow  = mt * 16 + (lane & 15);
            const int arx   = arow & 7;
            const uint32_t abase = (uint32_t)(arow * 128);
#pragma unroll
            for (int ks = 0; ks < 4; ++ks) {
                uint32_t ah[4], al[4];
                uint32_t chsel = (uint32_t)(((ks * 2 + (lane >> 4)) ^ arx) * 16);
                ldm4(ah, yhi_b + abase + chsel);
                ldm4(al, ylo_b + abase + chsel);
#pragma unroll
                for (int ntl = 0; ntl < 4; ++ntl) mma16816(acc[ntl], ah, bfr[ntl][ks]);
#pragma unroll
                for (int ntl = 0; ntl < 4; ++ntl) mma16816(acc[ntl], al, bfr[ntl][ks]);
            }
            // epilogue: relu + packed A-accumulation
            const int r0 = mt * 16 + (lane >> 2);
            double2 qa = *(const double2*)(rts4 + r0);
            double2 qb = *(const double2*)(rts4 + r0 + 8);
            const ull q0xy = __double_as_longlong(qa.x), q0zw = __double_as_longlong(qa.y);
            const ull q1xy = __double_as_longlong(qb.x), q1zw = __double_as_longlong(qb.y);
#pragma unroll
            for (int cc = 0; cc < 8; ++cc) {
                const int ntl = cc >> 1, c = cc & 1;
                float g0 = fmaxf(acc[ntl][c],     0.f);
                float g1 = fmaxf(acc[ntl][2 + c], 0.f);
                ull g0p = pk2f(g0, g0);
                ull g1p = pk2f(g1, g1);
                part01[cc] = fma2(g0p, q0xy, part01[cc]);
                part23[cc] = fma2(g0p, q0zw, part23[cc]);
                part01[cc] = fma2(g1p, q1xy, part01[cc]);
                part23[cc] = fma2(g1p, q1zw, part23[cc]);
            }
        }

        // unpack + reduce across lane-groups sharing (lane&3)
#pragma unroll
        for (int cc = 0; cc < 8; ++cc) {
            float2 u01 = upk2(part01[cc]);
            float2 u23 = upk2(part23[cc]);
            float pv[4] = {u01.x, u01.y, u23.x, u23.y};
#pragma unroll
            for (int d = 0; d < 4; ++d) {
                float v = pv[d];
                v += __shfl_xor_sync(0xffffffffu, v, 4);
                v += __shfl_xor_sync(0xffffffffu, v, 8);
                v += __shfl_xor_sync(0xffffffffu, v, 16);
                pv[d] = v;
            }
            if (lane < 4) {
                int e = w * 32 + (cc >> 1) * 8 + lane * 2 + (cc & 1);
                float4 Tv = T_s[h * 64 + (e & 63)];
                A_s[h][e] = make_float4(pv[0] + Tv.x, pv[1] + Tv.y,
                                        pv[2] + Tv.z, pv[3] + Tv.w);
            }
        }
    }
    __syncthreads();

    // ---- D[e,m] = sum_d A[e,d] * A[m,d] per sn-half ----
    const int e = t;
#pragma unroll
    for (int h = 0; h < 2; ++h) {
        float4 a = A_s[h][e];
        size_t gsn = (size_t)blockIdx.x * 2 + h;
        float4* op = (float4*)(out + (gsn * 128 + e) * 16);
#pragma unroll
        for (int m4 = 0; m4 < 4; ++m4) {
            float4 b0 = A_s[h][4 * m4 + 0];
            float4 b1 = A_s[h][4 * m4 + 1];
            float4 b2 = A_s[h][4 * m4 + 2];
            float4 b3 = A_s[h][4 * m4 + 3];
            float4 o;
            o.x = a.x * b0.x + a.y * b0.y + a.z * b0.z + a.w * b0.w;
            o.y = a.x * b1.x + a.y * b1.y + a.z * b1.z + a.w * b1.w;
            o.z = a.x * b2.x + a.y * b2.y + a.z * b2.z + a.w * b2.w;
            o.w = a.x * b3.x + a.y * b3.y + a.z * b3.z + a.w * b3.w;
            op[m4] = o;
        }
    }
}

// ---------------- launch -----------------------------------------------------
extern "C" void kernel_launch(void* const* d_in, const int* in_sizes, int n_in,
                              void* d_out, int out_size) {
    const float* inputs = (const float*)d_in[0];
    const int*   types  = (const int*)d_in[1];
    const int*   neigh  = (const int*)d_in[2];
    const float* length = (const float*)d_in[3];
    const float* ew0 = (const float*)d_in[4];
    const float* eb0 = (const float*)d_in[5];
    const float* ew1 = (const float*)d_in[6];
    const float* eb1 = (const float*)d_in[7];
    const float* fw0 = (const float*)d_in[8];
    const float* fb0 = (const float*)d_in[9];
    const float* fw1 = (const float*)d_in[10];
    const float* fb1 = (const float*)d_in[11];
    const float* gw0 = (const float*)d_in[12];
    const float* gb0 = (const float*)d_in[13];
    const float* gw1 = (const float*)d_in[14];
    const float* gb1 = (const float*)d_in[15];

    precompute_kernel<<<1, 128>>>(ew0, eb0, ew1, eb1, fw0, fb0, fw1, fb1, gw0, gb0, gw1);
    desc_kernel<<<NPAIR, 128>>>(inputs, types, neigh, length, gb1, (float*)d_out);
}

// round 10
// speedup vs baseline: 1.8145x; 1.2107x over previous
#include <cuda_runtime.h>
#include <cuda_fp16.h>
#include <cstdint>

#define SS 8
#define NN 2048
#define KK 64
#define NPAIR (SS * NN / 2)
#define PI_F 3.14159265358979323846f

// ---------------- precomputed tables (written by precompute_kernel) ----------
__device__ float g_td[4][31];      // td table per type-pair
__device__ float g_base[4][64];    // td @ gw0[:31] + gb0
__device__ float g_v[64];          // gw0[31,:]
// W^T fragments (fp16) in mma.sync B layout: [nt(16)][ks(4)][lane(32)]
__device__ uint2 g_bfrag[2048];

// ---------------- helpers ----------------------------------------------------
__device__ __forceinline__ uint32_t smem_u32(const void* p) {
    uint32_t a;
    asm("{ .reg .u64 t; cvta.to.shared.u64 t, %1; cvt.u32.u64 %0, t; }" : "=r"(a) : "l"(p));
    return a;
}
__device__ __forceinline__ void ldm4(uint32_t* r, uint32_t addr) {
    asm volatile("ldmatrix.sync.aligned.m8n8.x4.shared.b16 {%0,%1,%2,%3}, [%4];"
                 : "=r"(r[0]), "=r"(r[1]), "=r"(r[2]), "=r"(r[3]) : "r"(addr));
}
__device__ __forceinline__ void mma16816(float* c, const uint32_t* a, uint2 b) {
    asm volatile("mma.sync.aligned.m16n8k16.row.col.f32.f16.f16.f32 "
                 "{%0,%1,%2,%3}, {%4,%5,%6,%7}, {%8,%9}, {%0,%1,%2,%3};"
                 : "+f"(c[0]), "+f"(c[1]), "+f"(c[2]), "+f"(c[3])
                 : "r"(a[0]), "r"(a[1]), "r"(a[2]), "r"(a[3]), "r"(b.x), "r"(b.y));
}
__device__ __forceinline__ uint32_t pack_h2(float lo, float hi) {
    __half l = __float2half_rn(lo);
    __half h = __float2half_rn(hi);
    return (uint32_t)__half_as_ushort(l) | ((uint32_t)__half_as_ushort(h) << 16);
}
// packed f32x2
typedef unsigned long long ull;
__device__ __forceinline__ ull pk2f(float lo, float hi) {
    ull r; asm("mov.b64 %0, {%1, %2};" : "=l"(r) : "f"(lo), "f"(hi)); return r;
}
__device__ __forceinline__ ull fma2(ull a, ull b, ull c) {
    ull d; asm("fma.rn.f32x2 %0, %1, %2, %3;" : "=l"(d) : "l"(a), "l"(b), "l"(c)); return d;
}
__device__ __forceinline__ float2 upk2(ull v) {
    float2 r; asm("mov.b64 {%0, %1}, %2;" : "=f"(r.x), "=f"(r.y) : "l"(v)); return r;
}

// ---------------- parallel precompute: 4 type pairs + W fragment pack --------
__global__ void precompute_kernel(const float* __restrict__ ew0, const float* __restrict__ eb0,
                                  const float* __restrict__ ew1, const float* __restrict__ eb1,
                                  const float* __restrict__ fw0, const float* __restrict__ fb0,
                                  const float* __restrict__ fw1, const float* __restrict__ fb1,
                                  const float* __restrict__ gw0, const float* __restrict__ gb0,
                                  const float* __restrict__ gw1) {
    __shared__ float sh16[2][4][16];
    __shared__ float sh32[4][32];
    __shared__ float shf[4][32];
    __shared__ float shtd[4][31];
    const int t = threadIdx.x;

    {
        int rev = t >> 6, p = (t >> 4) & 3, i = t & 15;
        float a = (float)(p >> 1), b = (float)(p & 1);
        float x0 = rev ? b : a, x1 = rev ? a : b;
        sh16[rev][p][i] = fmaxf(x0 * ew0[i] + x1 * ew0[16 + i] + eb0[i], 0.f);
    }
    __syncthreads();
    {
        int p = t >> 5, o = t & 31;
        float s0 = eb1[o], s1 = eb1[o];
        for (int i = 0; i < 16; ++i) {
            s0 += sh16[0][p][i] * ew1[i * 32 + o];
            s1 += sh16[1][p][i] * ew1[i * 32 + o];
        }
        sh32[p][o] = fmaxf(s0, 0.f) + fmaxf(s1, 0.f);
    }
    __syncthreads();
    {
        int p = t >> 5, o = t & 31;
        float acc = fb0[o];
        for (int i = 0; i < 32; ++i) acc += sh32[p][i] * fw0[i * 32 + o];
        shf[p][o] = fmaxf(acc, 0.f);
    }
    __syncthreads();
    if (t < 124) {
        int p = t / 31, o = t % 31;
        float acc = fb1[o];
        for (int i = 0; i < 32; ++i) acc += shf[p][i] * fw1[i * 31 + o];
        float td = fmaxf(acc, 0.f);
        g_td[p][o] = td;
        shtd[p][o] = td;
    }
    __syncthreads();
    for (int it = 0; it < 2; ++it) {
        int idx = t + 128 * it;
        int p = idx >> 6, j = idx & 63;
        float acc = gb0[j];
        for (int i = 0; i < 31; ++i) acc += shtd[p][i] * gw0[i * 64 + j];
        g_base[p][j] = acc;
    }
    if (t < 64) g_v[t] = gw0[31 * 64 + t];

    // B fragments: fp16; mma.sync m16n8k16 col-major B layout
    for (int idx = t; idx < 2048; idx += 128) {
        int lane = idx & 31;
        int ks   = (idx >> 5) & 3;
        int nt   = idx >> 7;
        int e    = nt * 8 + (lane >> 2);
        int j0   = ks * 16 + (lane & 3) * 2;
        g_bfrag[idx] = make_uint2(
            pack_h2(gw1[j0 * 128 + e],       gw1[(j0 + 1) * 128 + e]),
            pack_h2(gw1[(j0 + 8) * 128 + e], gw1[(j0 + 9) * 128 + e]));
    }
}

// ---------------- fused main kernel: one CTA per 2 (s,n) pairs ---------------
__global__ __launch_bounds__(128, 4)
void desc_kernel(const float* __restrict__ inputs,
                 const int*   __restrict__ types,
                 const int*   __restrict__ neigh,
                 const float* __restrict__ length,
                 const float* __restrict__ gb1,
                 float*       __restrict__ out)
{
    // single Y panel: 128 rows x 64 fp16 (128B rows), 16B-chunk XOR swizzle
    __shared__ __align__(128) unsigned char ypan[128 * 128];
    __shared__ __align__(16) float4 rts4[128];
    __shared__ __align__(16) float base_s[4 * 68];
    __shared__ __align__(16) float v_s[64];
    __shared__ __align__(16) float td_s[4 * 34];
    __shared__ __align__(16) float4 T_s[128];        // [snh(2)][j(64)]
    __shared__ __align__(16) float4 A_s[2][128];

    const int t    = threadIdx.x;
    const int w    = t >> 5;
    const int lane = t & 31;

    // ---- B fragment preload ----
    uint2 bfr[4][4];
#pragma unroll
    for (int ntl = 0; ntl < 4; ++ntl)
#pragma unroll
        for (int ks = 0; ks < 4; ++ks)
            bfr[ntl][ks] = g_bfrag[(((w * 4 + ntl) * 4) + ks) * 32 + lane];

    // ---- stage tables ----
    for (int i = t; i < 256; i += 128) base_s[(i >> 6) * 68 + (i & 63)] = ((const float*)g_base)[i];
    if (t < 64) v_s[t] = g_v[t];
    for (int i = t; i < 124; i += 128) td_s[(i / 31) * 34 + (i % 31)] = ((const float*)g_td)[i];
    if (t < 4) { td_s[t * 34 + 31] = 0.f; td_s[t * 34 + 32] = 0.f; td_s[t * 34 + 33] = 0.f; }

    float b1v[8];
#pragma unroll
    for (int cc = 0; cc < 8; ++cc)
        b1v[cc] = gb1[w * 32 + (cc >> 1) * 8 + (lane & 3) * 2 + (cc & 1)];

    // ---- geometry ----
    const int sn = blockIdx.x * 2 + (t >> 6);
    const int s  = sn >> 11;
    const int n  = sn & (NN - 1);
    float sij; int pp;
    {
        int idx = neigh[(size_t)sn * KK + (t & 63)];
        bool msk = idx < 0;
        int i0 = msk ? 0 : idx;
        float Lx = length[0], Ly = length[1], Lz = length[2];
        const float* pc = inputs + ((size_t)s * NN + n) * 3;
        const float* pn = inputs + ((size_t)s * NN + i0) * 3;
        float dx = pn[0] - pc[0];
        float dy = pn[1] - pc[1];
        float dz = pn[2] - pc[2];
        dx -= Lx * rintf(dx / Lx);
        dy -= Ly * rintf(dy / Ly);
        dz -= Lz * rintf(dz / Lz);
        float rsq = dx * dx + dy * dy + dz * dz;
        float rs  = rsq > 0.f ? rsq : 1.0f;
        float inv = rsqrtf(rs);
        float r   = rs * inv;
        float sw;
        if (r < 6.0f)       sw = inv;
        else if (r < 12.0f) { float u = (r - 6.0f) * (1.0f / 6.0f);
                              sw = inv * (0.5f * __cosf(PI_F * u) + 0.5f); }
        else                sw = 0.f;
        bool valid = (!msk) && (rsq > 0.f);
        sij = valid ? sw : 0.f;
        float f = sij * inv;
        rts4[t] = make_float4(sij, dx * f, dy * f, dz * f);
        int ct = types[(size_t)s * NN + n];
        int nt = types[(size_t)s * NN + i0];
        pp = ct * 2 + nt;
    }
    __syncthreads();

    // ---- phase 2: y row t -> fp16, swizzled 16B-chunk stores ----
    {
        const int rx = t & 7;
        const float2* base2 = (const float2*)(base_s + pp * 68);
        const float2* v2    = (const float2*)v_s;
        const float2* td2   = (const float2*)(td_s + pp * 34);
#pragma unroll
        for (int c = 0; c < 8; ++c) {
            uint32_t wh[4];
#pragma unroll
            for (int q = 0; q < 4; ++q) {
                int jp = c * 4 + q;
                float2 b  = base2[jp];
                float2 vv = v2[jp];
                float2 td = td2[jp & 15];
                float y0 = fmaxf(fmaf(sij, vv.x, b.x), 0.f) + td.x;
                float y1 = fmaxf(fmaf(sij, vv.y, b.y), 0.f) + (((jp & 15) < 15) ? td.y : sij);
                wh[q] = pack_h2(y0, y1);
            }
            int off = t * 128 + (c ^ rx) * 16;
            *(uint4*)(ypan + off) = make_uint4(wh[0], wh[1], wh[2], wh[3]);
        }
    }
    __syncthreads();

    const __half* y16 = (const __half*)ypan;

    // ---- tail: T[j,d] = sum_k y[k,j] * rt[k,d]; packed f32x2 ----
    {
        const int snh = t >> 6, jt = t & 63;
        const int chunk = jt >> 3, jlow = jt & 7;
        const uint32_t ob = (uint32_t)(snh * 64 * 64 + jlow);
        ull T01 = 0ull, T23 = 0ull;
#pragma unroll
        for (int k = 0; k < 64; ++k) {
            uint32_t o = ob + (uint32_t)(k * 64 + ((chunk ^ (k & 7)) << 3));
            float y = __half2float(y16[o]);
            ull yp = pk2f(y, y);
            double2 q = *(const double2*)(rts4 + snh * 64 + k);
            T01 = fma2(yp, __double_as_longlong(q.x), T01);
            T23 = fma2(yp, __double_as_longlong(q.y), T23);
        }
        float2 a = upk2(T01), b = upk2(T23);
        T_s[t] = make_float4(a.x, a.y, b.x, b.y);
    }
    __syncthreads();

    const uint32_t y_b = smem_u32(ypan);

    // ---- MMA + fused epilogue: G = Yh * Wh, 4 mma per (mt,ks) ----
#pragma unroll
    for (int h = 0; h < 2; ++h) {
        ull part01[8], part23[8];
#pragma unroll
        for (int cc = 0; cc < 8; ++cc) { part01[cc] = 0ull; part23[cc] = 0ull; }

#pragma unroll
        for (int mtl = 0; mtl < 4; ++mtl) {
            const int mt = h * 4 + mtl;
            float acc[4][4];
#pragma unroll
            for (int ntl = 0; ntl < 4; ++ntl) {   // bias pre-folded
                acc[ntl][0] = b1v[ntl * 2];
                acc[ntl][1] = b1v[ntl * 2 + 1];
                acc[ntl][2] = b1v[ntl * 2];
                acc[ntl][3] = b1v[ntl * 2 + 1];
            }

            const int arow  = mt * 16 + (lane & 15);
            const int arx   = arow & 7;
            const uint32_t abase = (uint32_t)(arow * 128);
#pragma unroll
            for (int ks = 0; ks < 4; ++ks) {
                uint32_t ah[4];
                uint32_t chsel = (uint32_t)(((ks * 2 + (lane >> 4)) ^ arx) * 16);
                ldm4(ah, y_b + abase + chsel);
#pragma unroll
                for (int ntl = 0; ntl < 4; ++ntl) mma16816(acc[ntl], ah, bfr[ntl][ks]);
            }
            // epilogue: relu + packed A-accumulation
            const int r0 = mt * 16 + (lane >> 2);
            double2 qa = *(const double2*)(rts4 + r0);
            double2 qb = *(const double2*)(rts4 + r0 + 8);
            const ull q0xy = __double_as_longlong(qa.x), q0zw = __double_as_longlong(qa.y);
            const ull q1xy = __double_as_longlong(qb.x), q1zw = __double_as_longlong(qb.y);
#pragma unroll
            for (int cc = 0; cc < 8; ++cc) {
                const int ntl = cc >> 1, c = cc & 1;
                float g0 = fmaxf(acc[ntl][c],     0.f);
                float g1 = fmaxf(acc[ntl][2 + c], 0.f);
                ull g0p = pk2f(g0, g0);
                ull g1p = pk2f(g1, g1);
                part01[cc] = fma2(g0p, q0xy, part01[cc]);
                part23[cc] = fma2(g0p, q0zw, part23[cc]);
                part01[cc] = fma2(g1p, q1xy, part01[cc]);
                part23[cc] = fma2(g1p, q1zw, part23[cc]);
            }
        }

        // unpack + reduce across lane-groups sharing (lane&3)
#pragma unroll
        for (int cc = 0; cc < 8; ++cc) {
            float2 u01 = upk2(part01[cc]);
            float2 u23 = upk2(part23[cc]);
            float pv[4] = {u01.x, u01.y, u23.x, u23.y};
#pragma unroll
            for (int d = 0; d < 4; ++d) {
                float v = pv[d];
                v += __shfl_xor_sync(0xffffffffu, v, 4);
                v += __shfl_xor_sync(0xffffffffu, v, 8);
                v += __shfl_xor_sync(0xffffffffu, v, 16);
                pv[d] = v;
            }
            if (lane < 4) {
                int e = w * 32 + (cc >> 1) * 8 + lane * 2 + (cc & 1);
                float4 Tv = T_s[h * 64 + (e & 63)];
                A_s[h][e] = make_float4(pv[0] + Tv.x, pv[1] + Tv.y,
                                        pv[2] + Tv.z, pv[3] + Tv.w);
            }
        }
    }
    __syncthreads();

    // ---- D[e,m] = sum_d A[e,d] * A[m,d] per sn-half ----
    const int e = t;
#pragma unroll
    for (int h = 0; h < 2; ++h) {
        float4 a = A_s[h][e];
        size_t gsn = (size_t)blockIdx.x * 2 + h;
        float4* op = (float4*)(out + (gsn * 128 + e) * 16);
#pragma unroll
        for (int m4 = 0; m4 < 4; ++m4) {
            float4 b0 = A_s[h][4 * m4 + 0];
            float4 b1 = A_s[h][4 * m4 + 1];
            float4 b2 = A_s[h][4 * m4 + 2];
            float4 b3 = A_s[h][4 * m4 + 3];
            float4 o;
            o.x = a.x * b0.x + a.y * b0.y + a.z * b0.z + a.w * b0.w;
            o.y = a.x * b1.x + a.y * b1.y + a.z * b1.z + a.w * b1.w;
            o.z = a.x * b2.x + a.y * b2.y + a.z * b2.z + a.w * b2.w;
            o.w = a.x * b3.x + a.y * b3.y + a.z * b3.z + a.w * b3.w;
            op[m4] = o;
        }
    }
}

// ---------------- launch -----------------------------------------------------
extern "C" void kernel_launch(void* const* d_in, const int* in_sizes, int n_in,
                              void* d_out, int out_size) {
    const float* inputs = (const float*)d_in[0];
    const int*   types  = (const int*)d_in[1];
    const int*   neigh  = (const int*)d_in[2];
    const float* length = (const float*)d_in[3];
    const float* ew0 = (const float*)d_in[4];
    const float* eb0 = (const float*)d_in[5];
    const float* ew1 = (const float*)d_in[6];
    const float* eb1 = (const float*)d_in[7];
    const float* fw0 = (const float*)d_in[8];
    const float* fb0 = (const float*)d_in[9];
    const float* fw1 = (const float*)d_in[10];
    const float* fb1 = (const float*)d_in[11];
    const float* gw0 = (const float*)d_in[12];
    const float* gb0 = (const float*)d_in[13];
    const float* gw1 = (const float*)d_in[14];
    const float* gb1 = (const float*)d_in[15];

    precompute_kernel<<<1, 128>>>(ew0, eb0, ew1, eb1, fw0, fb0, fw1, fb1, gw0, gb0, gw1);
    desc_kernel<<<NPAIR, 128>>>(inputs, types, neigh, length, gb1, (float*)d_out);
}

// round 11
// speedup vs baseline: 1.8669x; 1.0289x over previous
#include <cuda_runtime.h>
#include <cuda_fp16.h>
#include <cstdint>

#define SS 8
#define NN 2048
#define KK 64
#define NPAIR (SS * NN / 2)
#define PI_F 3.14159265358979323846f

// ---------------- precomputed tables (written by precompute_kernel) ----------
__device__ float g_td[4][31];      // td table per type-pair
__device__ float g_base[4][64];    // td @ gw0[:31] + gb0
__device__ float g_v[64];          // gw0[31,:]
// W^T fragments (fp16) in mma.sync B layout: [nt(16)][ks(4)][lane(32)]
__device__ uint2 g_bfrag[2048];

// ---------------- helpers ----------------------------------------------------
__device__ __forceinline__ uint32_t smem_u32(const void* p) {
    uint32_t a;
    asm("{ .reg .u64 t; cvta.to.shared.u64 t, %1; cvt.u32.u64 %0, t; }" : "=r"(a) : "l"(p));
    return a;
}
__device__ __forceinline__ void ldm4(uint32_t* r, uint32_t addr) {
    asm volatile("ldmatrix.sync.aligned.m8n8.x4.shared.b16 {%0,%1,%2,%3}, [%4];"
                 : "=r"(r[0]), "=r"(r[1]), "=r"(r[2]), "=r"(r[3]) : "r"(addr));
}
__device__ __forceinline__ void mma16816(float* c, const uint32_t* a, uint2 b) {
    asm volatile("mma.sync.aligned.m16n8k16.row.col.f32.f16.f16.f32 "
                 "{%0,%1,%2,%3}, {%4,%5,%6,%7}, {%8,%9}, {%0,%1,%2,%3};"
                 : "+f"(c[0]), "+f"(c[1]), "+f"(c[2]), "+f"(c[3])
                 : "r"(a[0]), "r"(a[1]), "r"(a[2]), "r"(a[3]), "r"(b.x), "r"(b.y));
}
__device__ __forceinline__ uint32_t pack_h2(float lo, float hi) {
    __half l = __float2half_rn(lo);
    __half h = __float2half_rn(hi);
    return (uint32_t)__half_as_ushort(l) | ((uint32_t)__half_as_ushort(h) << 16);
}
// packed f32x2
typedef unsigned long long ull;
__device__ __forceinline__ ull pk2f(float lo, float hi) {
    ull r; asm("mov.b64 %0, {%1, %2};" : "=l"(r) : "f"(lo), "f"(hi)); return r;
}
__device__ __forceinline__ ull fma2(ull a, ull b, ull c) {
    ull d; asm("fma.rn.f32x2 %0, %1, %2, %3;" : "=l"(d) : "l"(a), "l"(b), "l"(c)); return d;
}
__device__ __forceinline__ float2 upk2(ull v) {
    float2 r; asm("mov.b64 {%0, %1}, %2;" : "=f"(r.x), "=f"(r.y) : "l"(v)); return r;
}

// ---------------- parallel precompute: 4 type pairs + W fragment pack --------
__global__ void precompute_kernel(const float* __restrict__ ew0, const float* __restrict__ eb0,
                                  const float* __restrict__ ew1, const float* __restrict__ eb1,
                                  const float* __restrict__ fw0, const float* __restrict__ fb0,
                                  const float* __restrict__ fw1, const float* __restrict__ fb1,
                                  const float* __restrict__ gw0, const float* __restrict__ gb0,
                                  const float* __restrict__ gw1) {
    __shared__ float sh16[2][4][16];
    __shared__ float sh32[4][32];
    __shared__ float shf[4][32];
    __shared__ float shtd[4][31];
    const int t = threadIdx.x;

    {
        int rev = t >> 6, p = (t >> 4) & 3, i = t & 15;
        float a = (float)(p >> 1), b = (float)(p & 1);
        float x0 = rev ? b : a, x1 = rev ? a : b;
        sh16[rev][p][i] = fmaxf(x0 * ew0[i] + x1 * ew0[16 + i] + eb0[i], 0.f);
    }
    __syncthreads();
    {
        int p = t >> 5, o = t & 31;
        float s0 = eb1[o], s1 = eb1[o];
        for (int i = 0; i < 16; ++i) {
            s0 += sh16[0][p][i] * ew1[i * 32 + o];
            s1 += sh16[1][p][i] * ew1[i * 32 + o];
        }
        sh32[p][o] = fmaxf(s0, 0.f) + fmaxf(s1, 0.f);
    }
    __syncthreads();
    {
        int p = t >> 5, o = t & 31;
        float acc = fb0[o];
        for (int i = 0; i < 32; ++i) acc += sh32[p][i] * fw0[i * 32 + o];
        shf[p][o] = fmaxf(acc, 0.f);
    }
    __syncthreads();
    if (t < 124) {
        int p = t / 31, o = t % 31;
        float acc = fb1[o];
        for (int i = 0; i < 32; ++i) acc += shf[p][i] * fw1[i * 31 + o];
        float td = fmaxf(acc, 0.f);
        g_td[p][o] = td;
        shtd[p][o] = td;
    }
    __syncthreads();
    for (int it = 0; it < 2; ++it) {
        int idx = t + 128 * it;
        int p = idx >> 6, j = idx & 63;
        float acc = gb0[j];
        for (int i = 0; i < 31; ++i) acc += shtd[p][i] * gw0[i * 64 + j];
        g_base[p][j] = acc;
    }
    if (t < 64) g_v[t] = gw0[31 * 64 + t];

    // B fragments: fp16; mma.sync m16n8k16 col-major B layout
    for (int idx = t; idx < 2048; idx += 128) {
        int lane = idx & 31;
        int ks   = (idx >> 5) & 3;
        int nt   = idx >> 7;
        int e    = nt * 8 + (lane >> 2);
        int j0   = ks * 16 + (lane & 3) * 2;
        g_bfrag[idx] = make_uint2(
            pack_h2(gw1[j0 * 128 + e],       gw1[(j0 + 1) * 128 + e]),
            pack_h2(gw1[(j0 + 8) * 128 + e], gw1[(j0 + 9) * 128 + e]));
    }
}

// ---------------- fused main kernel: one CTA per 2 (s,n) pairs ---------------
__global__ __launch_bounds__(128, 4)
void desc_kernel(const float* __restrict__ inputs,
                 const int*   __restrict__ types,
                 const int*   __restrict__ neigh,
                 const float* __restrict__ length,
                 const float* __restrict__ gb1,
                 float*       __restrict__ out)
{
    // single Y panel: 128 rows x 64 fp16 (128B rows), 16B-chunk XOR swizzle
    __shared__ __align__(128) unsigned char ypan[128 * 128];
    __shared__ __align__(16) float4 rts4[128];
    __shared__ __align__(16) float base_s[4 * 68];
    __shared__ __align__(16) float v_s[64];
    __shared__ __align__(16) float td_s[4 * 34];
    __shared__ __align__(16) float4 T_part[2][128];  // [kh][snh*64 + j]
    __shared__ __align__(16) float4 A_s[2][128];

    const int t    = threadIdx.x;
    const int w    = t >> 5;
    const int lane = t & 31;

    // ---- B fragment preload ----
    uint2 bfr[4][4];
#pragma unroll
    for (int ntl = 0; ntl < 4; ++ntl)
#pragma unroll
        for (int ks = 0; ks < 4; ++ks)
            bfr[ntl][ks] = g_bfrag[(((w * 4 + ntl) * 4) + ks) * 32 + lane];

    // ---- stage tables ----
    for (int i = t; i < 256; i += 128) base_s[(i >> 6) * 68 + (i & 63)] = ((const float*)g_base)[i];
    if (t < 64) v_s[t] = g_v[t];
    for (int i = t; i < 124; i += 128) td_s[(i / 31) * 34 + (i % 31)] = ((const float*)g_td)[i];
    if (t < 4) { td_s[t * 34 + 31] = 0.f; td_s[t * 34 + 32] = 0.f; td_s[t * 34 + 33] = 0.f; }

    float b1v[8];
#pragma unroll
    for (int cc = 0; cc < 8; ++cc)
        b1v[cc] = gb1[w * 32 + (cc >> 1) * 8 + (lane & 3) * 2 + (cc & 1)];

    // ---- geometry ----
    const int sn = blockIdx.x * 2 + (t >> 6);
    const int s  = sn >> 11;
    const int n  = sn & (NN - 1);
    float sij; int pp;
    {
        int idx = neigh[(size_t)sn * KK + (t & 63)];
        bool msk = idx < 0;
        int i0 = msk ? 0 : idx;
        float Lx = length[0], Ly = length[1], Lz = length[2];
        const float* pc = inputs + ((size_t)s * NN + n) * 3;
        const float* pn = inputs + ((size_t)s * NN + i0) * 3;
        float dx = pn[0] - pc[0];
        float dy = pn[1] - pc[1];
        float dz = pn[2] - pc[2];
        dx -= Lx * rintf(dx / Lx);
        dy -= Ly * rintf(dy / Ly);
        dz -= Lz * rintf(dz / Lz);
        float rsq = dx * dx + dy * dy + dz * dz;
        float rs  = rsq > 0.f ? rsq : 1.0f;
        float inv = rsqrtf(rs);
        float r   = rs * inv;
        float sw;
        if (r < 6.0f)       sw = inv;
        else if (r < 12.0f) { float u = (r - 6.0f) * (1.0f / 6.0f);
                              sw = inv * (0.5f * __cosf(PI_F * u) + 0.5f); }
        else                sw = 0.f;
        bool valid = (!msk) && (rsq > 0.f);
        sij = valid ? sw : 0.f;
        float f = sij * inv;
        rts4[t] = make_float4(sij, dx * f, dy * f, dz * f);
        int ct = types[(size_t)s * NN + n];
        int nt = types[(size_t)s * NN + i0];
        pp = ct * 2 + nt;
    }
    __syncthreads();

    // ---- phase 2: y row t -> fp16, swizzled 16B-chunk stores ----
    {
        const int rx = t & 7;
        const float2* base2 = (const float2*)(base_s + pp * 68);
        const float2* v2    = (const float2*)v_s;
        const float2* td2   = (const float2*)(td_s + pp * 34);
#pragma unroll
        for (int c = 0; c < 8; ++c) {
            uint32_t wh[4];
#pragma unroll
            for (int q = 0; q < 4; ++q) {
                int jp = c * 4 + q;
                float2 b  = base2[jp];
                float2 vv = v2[jp];
                float2 td = td2[jp & 15];
                float y0 = fmaxf(fmaf(sij, vv.x, b.x), 0.f) + td.x;
                float y1 = fmaxf(fmaf(sij, vv.y, b.y), 0.f) + (((jp & 15) < 15) ? td.y : sij);
                wh[q] = pack_h2(y0, y1);
            }
            int off = t * 128 + (c ^ rx) * 16;
            *(uint4*)(ypan + off) = make_uint4(wh[0], wh[1], wh[2], wh[3]);
        }
    }
    __syncthreads();

    // ---- tail partials: T_part[kh][snh*64+j] = sum_{k in half} y[k,j]*rt[k,:] ----
    // warp = (snh, kh); lane = j-pair. half2 y-loads, broadcast rt loads.
    {
        const int snh = t >> 6;          // warps 0,1 -> pair 0; warps 2,3 -> pair 1
        const int kh  = (t >> 5) & 1;    // warp-level k-half
        const int jp  = lane;            // j = 2*jp, 2*jp+1
        const int chunk = jp >> 2, pos = jp & 3;
        const uint32_t* y32 = (const uint32_t*)ypan;
        const int rbase = snh * 64 + kh * 32;
        ull Tj0a = 0ull, Tj0b = 0ull, Tj1a = 0ull, Tj1b = 0ull;
#pragma unroll
        for (int i = 0; i < 32; ++i) {
            const int row = rbase + i;
            uint32_t o = (uint32_t)(row * 32 + ((chunk ^ (row & 7)) << 2) + pos);
            uint32_t yv = y32[o];
            float2 yf = __half22float2(*(const __half2*)&yv);
            ull y0p = pk2f(yf.x, yf.x);
            ull y1p = pk2f(yf.y, yf.y);
            double2 q = *(const double2*)(rts4 + row);
            ull qxy = __double_as_longlong(q.x), qzw = __double_as_longlong(q.y);
            Tj0a = fma2(y0p, qxy, Tj0a);
            Tj0b = fma2(y0p, qzw, Tj0b);
            Tj1a = fma2(y1p, qxy, Tj1a);
            Tj1b = fma2(y1p, qzw, Tj1b);
        }
        float2 a0 = upk2(Tj0a), b0 = upk2(Tj0b);
        float2 a1 = upk2(Tj1a), b1 = upk2(Tj1b);
        T_part[kh][snh * 64 + 2 * jp]     = make_float4(a0.x, a0.y, b0.x, b0.y);
        T_part[kh][snh * 64 + 2 * jp + 1] = make_float4(a1.x, a1.y, b1.x, b1.y);
    }
    __syncthreads();

    const uint32_t y_b = smem_u32(ypan);

    // ---- MMA + fused epilogue: G = Yh * Wh, 4 mma per (mt,ks) ----
#pragma unroll
    for (int h = 0; h < 2; ++h) {
        ull part01[8], part23[8];
#pragma unroll
        for (int cc = 0; cc < 8; ++cc) { part01[cc] = 0ull; part23[cc] = 0ull; }

#pragma unroll
        for (int mtl = 0; mtl < 4; ++mtl) {
            const int mt = h * 4 + mtl;
            float acc[4][4];
#pragma unroll
            for (int ntl = 0; ntl < 4; ++ntl) {   // bias pre-folded
                acc[ntl][0] = b1v[ntl * 2];
                acc[ntl][1] = b1v[ntl * 2 + 1];
                acc[ntl][2] = b1v[ntl * 2];
                acc[ntl][3] = b1v[ntl * 2 + 1];
            }

            const int arow  = mt * 16 + (lane & 15);
            const int arx   = arow & 7;
            const uint32_t abase = (uint32_t)(arow * 128);
#pragma unroll
            for (int ks = 0; ks < 4; ++ks) {
                uint32_t ah[4];
                uint32_t chsel = (uint32_t)(((ks * 2 + (lane >> 4)) ^ arx) * 16);
                ldm4(ah, y_b + abase + chsel);
#pragma unroll
                for (int ntl = 0; ntl < 4; ++ntl) mma16816(acc[ntl], ah, bfr[ntl][ks]);
            }
            // epilogue: relu + packed A-accumulation
            const int r0 = mt * 16 + (lane >> 2);
            double2 qa = *(const double2*)(rts4 + r0);
            double2 qb = *(const double2*)(rts4 + r0 + 8);
            const ull q0xy = __double_as_longlong(qa.x), q0zw = __double_as_longlong(qa.y);
            const ull q1xy = __double_as_longlong(qb.x), q1zw = __double_as_longlong(qb.y);
#pragma unroll
            for (int cc = 0; cc < 8; ++cc) {
                const int ntl = cc >> 1, c = cc & 1;
                float g0 = fmaxf(acc[ntl][c],     0.f);
                float g1 = fmaxf(acc[ntl][2 + c], 0.f);
                ull g0p = pk2f(g0, g0);
                ull g1p = pk2f(g1, g1);
                part01[cc] = fma2(g0p, q0xy, part01[cc]);
                part23[cc] = fma2(g0p, q0zw, part23[cc]);
                part01[cc] = fma2(g1p, q1xy, part01[cc]);
                part23[cc] = fma2(g1p, q1zw, part23[cc]);
            }
        }

        // unpack + reduce across lane-groups sharing (lane&3)
#pragma unroll
        for (int cc = 0; cc < 8; ++cc) {
            float2 u01 = upk2(part01[cc]);
            float2 u23 = upk2(part23[cc]);
            float pv[4] = {u01.x, u01.y, u23.x, u23.y};
#pragma unroll
            for (int d = 0; d < 4; ++d) {
                float v = pv[d];
                v += __shfl_xor_sync(0xffffffffu, v, 4);
                v += __shfl_xor_sync(0xffffffffu, v, 8);
                v += __shfl_xor_sync(0xffffffffu, v, 16);
                pv[d] = v;
            }
            if (lane < 4) {
                int e = w * 32 + (cc >> 1) * 8 + lane * 2 + (cc & 1);
                float4 Ta = T_part[0][h * 64 + (e & 63)];
                float4 Tb = T_part[1][h * 64 + (e & 63)];
                A_s[h][e] = make_float4(pv[0] + Ta.x + Tb.x, pv[1] + Ta.y + Tb.y,
                                        pv[2] + Ta.z + Tb.z, pv[3] + Ta.w + Tb.w);
            }
        }
    }
    __syncthreads();

    // ---- D[e,m] = sum_d A[e,d] * A[m,d] per sn-half ----
    const int e = t;
#pragma unroll
    for (int h = 0; h < 2; ++h) {
        float4 a = A_s[h][e];
        size_t gsn = (size_t)blockIdx.x * 2 + h;
        float4* op = (float4*)(out + (gsn * 128 + e) * 16);
#pragma unroll
        for (int m4 = 0; m4 < 4; ++m4) {
            float4 b0 = A_s[h][4 * m4 + 0];
            float4 b1 = A_s[h][4 * m4 + 1];
            float4 b2 = A_s[h][4 * m4 + 2];
            float4 b3 = A_s[h][4 * m4 + 3];
            float4 o;
            o.x = a.x * b0.x + a.y * b0.y + a.z * b0.z + a.w * b0.w;
            o.y = a.x * b1.x + a.y * b1.y + a.z * b1.z + a.w * b1.w;
            o.z = a.x * b2.x + a.y * b2.y + a.z * b2.z + a.w * b2.w;
            o.w = a.x * b3.x + a.y * b3.y + a.z * b3.z + a.w * b3.w;
            op[m4] = o;
        }
    }
}

// ---------------- launch -----------------------------------------------------
extern "C" void kernel_launch(void* const* d_in, const int* in_sizes, int n_in,
                              void* d_out, int out_size) {
    const float* inputs = (const float*)d_in[0];
    const int*   types  = (const int*)d_in[1];
    const int*   neigh  = (const int*)d_in[2];
    const float* length = (const float*)d_in[3];
    const float* ew0 = (const float*)d_in[4];
    const float* eb0 = (const float*)d_in[5];
    const float* ew1 = (const float*)d_in[6];
    const float* eb1 = (const float*)d_in[7];
    const float* fw0 = (const float*)d_in[8];
    const float* fb0 = (const float*)d_in[9];
    const float* fw1 = (const float*)d_in[10];
    const float* fb1 = (const float*)d_in[11];
    const float* gw0 = (const float*)d_in[12];
    const float* gb0 = (const float*)d_in[13];
    const float* gw1 = (const float*)d_in[14];
    const float* gb1 = (const float*)d_in[15];

    precompute_kernel<<<1, 128>>>(ew0, eb0, ew1, eb1, fw0, fb0, fw1, fb1, gw0, gb0, gw1);
    desc_kernel<<<NPAIR, 128>>>(inputs, types, neigh, length, gb1, (float*)d_out);
}